// round 1
// baseline (speedup 1.0000x reference)
#include <cuda_runtime.h>
#include <math.h>

// ---------------------------------------------------------------------------
// Problem constants
// ---------------------------------------------------------------------------
#define BATCH   8
#define SEQT    150
#define MTOT    1200            // BATCH*SEQT
#define DIMC    1024
#define DINC    2048            // D_IN
#define DSTATE  16
#define DTRANK  64
#define XDBLC   96              // DT_RANK + 2*D_STATE
#define INNERC  4096            // HEADS * DIM_HEAD
#define MLPC    4096
#define DEPTHC  5

// ---------------------------------------------------------------------------
// Scratch (no allocations allowed -> __device__ globals)
// ---------------------------------------------------------------------------
__device__ float g_norm [MTOT * DIMC];          // 4.9 MB
__device__ float g_xz   [MTOT * 2 * DINC];      // 19.7 MB
__device__ float g_xc   [MTOT * DINC];          // 9.8 MB  (post conv+silu)
__device__ float g_xdbl [MTOT * XDBLC];         // 0.46 MB
__device__ float g_dt   [MTOT * DINC];          // 9.8 MB  (post softplus)
__device__ float g_y    [MTOT * DINC];          // 9.8 MB  (scan output)
__device__ float g_qkv  [MTOT * 3 * INNERC];    // 59 MB
__device__ float g_attn [MTOT * INNERC];        // 19.7 MB
__device__ float g_ffn  [MTOT * MLPC];          // 19.7 MB

// ---------------------------------------------------------------------------
// Math helpers
// ---------------------------------------------------------------------------
__device__ __forceinline__ float geluf(float x) {
    return 0.5f * x * (1.0f + erff(x * 0.70710678118654752f));
}
__device__ __forceinline__ float softplusf(float x) {
    // stable: max(x,0) + log1p(exp(-|x|))
    return fmaxf(x, 0.0f) + log1pf(__expf(-fabsf(x)));
}
__device__ __forceinline__ float siluf(float x) {
    return x / (1.0f + __expf(-x));
}

// ---------------------------------------------------------------------------
// Generic NT GEMM: C[M,N] (+)= epi( A[M,K] * B[N,K]^T + bias )
// 128x128 tile, BK=16, 256 threads, 8x8 microtile. Requires K % 16 == 0 and
// all row strides to be multiples of 4 floats (true for every call here).
// EPI: 0=store  1=+bias  2=gelu(+bias)  3=C+=acc(+bias)  4=C+=gelu(acc+bias)
//      5=softplus(acc+bias)
// ---------------------------------------------------------------------------
template <int EPI>
__global__ void __launch_bounds__(256)
gemm_nt(const float* __restrict__ A, int lda,
        const float* __restrict__ B, int ldb,
        const float* __restrict__ bias,
        float* __restrict__ C, int ldc,
        int M, int N, int K)
{
    __shared__ __align__(16) float As[16][132];
    __shared__ __align__(16) float Bs[16][132];

    const int m0  = blockIdx.y * 128;
    const int n0  = blockIdx.x * 128;
    const int tid = threadIdx.x;
    const int tx  = tid & 15;
    const int ty  = tid >> 4;

    float acc[8][8];
#pragma unroll
    for (int i = 0; i < 8; i++)
#pragma unroll
        for (int j = 0; j < 8; j++) acc[i][j] = 0.0f;

    for (int k0 = 0; k0 < K; k0 += 16) {
#pragma unroll
        for (int r = 0; r < 2; r++) {
            const int idx = tid + r * 256;      // 0..511
            const int row = idx >> 2;           // 0..127
            const int kq  = (idx & 3) << 2;     // 0,4,8,12
            float4 va = make_float4(0.f, 0.f, 0.f, 0.f);
            if (m0 + row < M)
                va = *reinterpret_cast<const float4*>(&A[(size_t)(m0 + row) * lda + k0 + kq]);
            As[kq + 0][row] = va.x; As[kq + 1][row] = va.y;
            As[kq + 2][row] = va.z; As[kq + 3][row] = va.w;
            float4 vb = make_float4(0.f, 0.f, 0.f, 0.f);
            if (n0 + row < N)
                vb = *reinterpret_cast<const float4*>(&B[(size_t)(n0 + row) * ldb + k0 + kq]);
            Bs[kq + 0][row] = vb.x; Bs[kq + 1][row] = vb.y;
            Bs[kq + 2][row] = vb.z; Bs[kq + 3][row] = vb.w;
        }
        __syncthreads();
#pragma unroll
        for (int kk = 0; kk < 16; kk++) {
            float a[8], b[8];
            *reinterpret_cast<float4*>(&a[0]) = *reinterpret_cast<const float4*>(&As[kk][ty * 8]);
            *reinterpret_cast<float4*>(&a[4]) = *reinterpret_cast<const float4*>(&As[kk][ty * 8 + 4]);
            *reinterpret_cast<float4*>(&b[0]) = *reinterpret_cast<const float4*>(&Bs[kk][tx * 8]);
            *reinterpret_cast<float4*>(&b[4]) = *reinterpret_cast<const float4*>(&Bs[kk][tx * 8 + 4]);
#pragma unroll
            for (int i = 0; i < 8; i++)
#pragma unroll
                for (int j = 0; j < 8; j++)
                    acc[i][j] = fmaf(a[i], b[j], acc[i][j]);
        }
        __syncthreads();
    }

#pragma unroll
    for (int i = 0; i < 8; i++) {
        const int m = m0 + ty * 8 + i;
        if (m >= M) continue;
#pragma unroll
        for (int j = 0; j < 8; j++) {
            const int n = n0 + tx * 8 + j;
            if (n >= N) continue;
            const size_t o = (size_t)m * ldc + n;
            float v = acc[i][j];
            if (EPI == 0)      C[o] = v;
            else if (EPI == 1) C[o] = v + bias[n];
            else if (EPI == 2) C[o] = geluf(v + bias[n]);
            else if (EPI == 3) C[o] = C[o] + v + (bias ? bias[n] : 0.0f);
            else if (EPI == 4) C[o] = C[o] + geluf(v + bias[n]);
            else if (EPI == 5) C[o] = softplusf(v + bias[n]);
        }
    }
}

// ---------------------------------------------------------------------------
// Skinny GEMM for x_proj: C[1200,96] = A[1200,2048] * B[96,2048]^T
// 16-row tiles -> 75 blocks (vs 10 with the generic tiler).
// ---------------------------------------------------------------------------
__global__ void __launch_bounds__(256)
gemm_xproj(const float* __restrict__ A, const float* __restrict__ B,
           float* __restrict__ C)
{
    __shared__ float As[16][33];
    __shared__ float Bs[96][33];
    const int m0  = blockIdx.x * 16;
    const int tid = threadIdx.x;
    const int ml  = tid >> 4;           // 0..15
    const int nb  = (tid & 15) * 6;     // 0..90

    float acc[6] = {0.f, 0.f, 0.f, 0.f, 0.f, 0.f};

    for (int k0 = 0; k0 < 2048; k0 += 32) {
#pragma unroll
        for (int u = 0; u < 2; u++) {
            const int idx = tid + u * 256;      // 0..511
            const int r = idx >> 5, kk = idx & 31;
            As[r][kk] = A[(size_t)(m0 + r) * 2048 + k0 + kk];
        }
#pragma unroll
        for (int u = 0; u < 12; u++) {
            const int idx = tid + u * 256;      // 0..3071
            const int r = idx >> 5, kk = idx & 31;
            Bs[r][kk] = B[(size_t)r * 2048 + k0 + kk];
        }
        __syncthreads();
#pragma unroll
        for (int kk = 0; kk < 32; kk++) {
            const float a = As[ml][kk];
#pragma unroll
            for (int j = 0; j < 6; j++)
                acc[j] = fmaf(a, Bs[nb + j][kk], acc[j]);
        }
        __syncthreads();
    }
#pragma unroll
    for (int j = 0; j < 6; j++)
        C[(size_t)(m0 + ml) * 96 + nb + j] = acc[j];
}

// ---------------------------------------------------------------------------
// LayerNorm: one block per row of 1024
// ---------------------------------------------------------------------------
__global__ void __launch_bounds__(256)
ln_kernel(const float* __restrict__ x, const float* __restrict__ w,
          const float* __restrict__ b, float* __restrict__ out)
{
    const int row = blockIdx.x;
    const int tid = threadIdx.x;
    const float* xr = x + (size_t)row * DIMC;
    __shared__ float red[8];

    float v[4];
    float s = 0.f;
#pragma unroll
    for (int u = 0; u < 4; u++) { v[u] = xr[tid + u * 256]; s += v[u]; }
#pragma unroll
    for (int o = 16; o; o >>= 1) s += __shfl_xor_sync(0xffffffffu, s, o);
    if ((tid & 31) == 0) red[tid >> 5] = s;
    __syncthreads();
    float tot = 0.f;
#pragma unroll
    for (int u = 0; u < 8; u++) tot += red[u];
    const float mu = tot * (1.0f / 1024.0f);

    float s2 = 0.f;
#pragma unroll
    for (int u = 0; u < 4; u++) { const float d = v[u] - mu; s2 += d * d; }
    __syncthreads();
#pragma unroll
    for (int o = 16; o; o >>= 1) s2 += __shfl_xor_sync(0xffffffffu, s2, o);
    if ((tid & 31) == 0) red[tid >> 5] = s2;
    __syncthreads();
    float tot2 = 0.f;
#pragma unroll
    for (int u = 0; u < 8; u++) tot2 += red[u];
    const float rstd = rsqrtf(tot2 * (1.0f / 1024.0f) + 1e-5f);

    float* orow = out + (size_t)row * DIMC;
#pragma unroll
    for (int u = 0; u < 4; u++) {
        const int c = tid + u * 256;
        orow[c] = (v[u] - mu) * rstd * w[c] + b[c];
    }
}

// ---------------------------------------------------------------------------
// Depthwise causal conv (width 4) + bias + silu.  xz holds [xc | z] (4096 wide)
// ---------------------------------------------------------------------------
__global__ void __launch_bounds__(256)
conv_kernel(const float* __restrict__ xz, const float* __restrict__ cw,
            const float* __restrict__ cb, float* __restrict__ out)
{
    const int m = blockIdx.x;                        // 0..1199
    const int d = blockIdx.y * 256 + threadIdx.x;    // 0..2047
    const int b = m / SEQT, t = m % SEQT;
    float acc = cb[d];
#pragma unroll
    for (int j = 0; j < 4; j++) {
        const int tt = t + j - 3;
        if (tt >= 0)
            acc = fmaf(cw[d * 4 + j], xz[((size_t)(b * SEQT + tt)) * 4096 + d], acc);
    }
    out[(size_t)m * DINC + d] = siluf(acc);
}

// ---------------------------------------------------------------------------
// Selective scan. Block = 16 d-lanes x 16 states, grid (128, B).
// Fused epilogue: y = (scan + D*xc) * silu(z)
// ---------------------------------------------------------------------------
__global__ void __launch_bounds__(256)
scan_kernel(const float* __restrict__ dt, const float* __restrict__ xc,
            const float* __restrict__ xdbl, const float* __restrict__ A_log,
            const float* __restrict__ Dw, const float* __restrict__ xz,
            float* __restrict__ y)
{
    const int tid = threadIdx.x;
    const int dl = tid & 15;        // d within block
    const int s  = tid >> 4;        // state index 0..15
    const int d  = blockIdx.x * 16 + dl;
    const int b  = blockIdx.y;

    const float a = -expf(A_log[d * 16 + s]);
    float h = 0.f;
    float Dv = (s == 0) ? Dw[d] : 0.f;

    __shared__ float red[16][17];

    for (int t = 0; t < SEQT; t++) {
        const size_t base = (size_t)(b * SEQT + t);
        const float dtv = dt[base * DINC + d];
        const float xcv = xc[base * DINC + d];
        const float Bv  = xdbl[base * XDBLC + 64 + s];
        const float Cv  = xdbl[base * XDBLC + 80 + s];
        h = __expf(dtv * a) * h + dtv * Bv * xcv;
        red[s][dl] = h * Cv;
        __syncthreads();
        if (s == 0) {
            float sum = 0.f;
#pragma unroll
            for (int ss = 0; ss < 16; ss++) sum += red[ss][dl];
            const float zv = xz[base * 4096 + 2048 + d];
            y[base * DINC + d] = (sum + Dv * xcv) * (zv / (1.0f + __expf(-zv)));
        }
        __syncthreads();
    }
}

// ---------------------------------------------------------------------------
// Causal attention, one block per (query row i, head, batch).
// HEADS=4, DIM_HEAD=1024, qkv row layout: [q(4096) | k(4096) | v(4096)]
// ---------------------------------------------------------------------------
__global__ void __launch_bounds__(256)
attn_kernel(const float* __restrict__ qkv, float* __restrict__ out)
{
    const int i  = blockIdx.x;
    const int hh = blockIdx.y;
    const int b  = blockIdx.z;
    const int tid  = threadIdx.x;
    const int lane = tid & 31;
    const int w    = tid >> 5;

    __shared__ float qs[1024];
    __shared__ float probs[152];
    __shared__ float s_inv;

    const size_t hoff = (size_t)hh * 1024;
    const float* qrow = qkv + ((size_t)(b * SEQT + i)) * 12288 + hoff;
#pragma unroll
    for (int u = 0; u < 4; u++) qs[tid + u * 256] = qrow[tid + u * 256];
    __syncthreads();

    const int nj = i + 1;
    for (int j = w; j < nj; j += 8) {
        const float* krow = qkv + ((size_t)(b * SEQT + j)) * 12288 + 4096 + hoff;
        float sdot = 0.f;
        for (int u = lane; u < 1024; u += 32) sdot = fmaf(qs[u], krow[u], sdot);
#pragma unroll
        for (int o = 16; o; o >>= 1) sdot += __shfl_xor_sync(0xffffffffu, sdot, o);
        if (lane == 0) probs[j] = sdot * 0.03125f;   // 1/sqrt(1024)
    }
    __syncthreads();

    if (w == 0) {
        float mx = -3.0e38f;
        for (int j = lane; j < nj; j += 32) mx = fmaxf(mx, probs[j]);
#pragma unroll
        for (int o = 16; o; o >>= 1) mx = fmaxf(mx, __shfl_xor_sync(0xffffffffu, mx, o));
        float sm = 0.f;
        for (int j = lane; j < nj; j += 32) {
            const float e = __expf(probs[j] - mx);
            probs[j] = e;
            sm += e;
        }
#pragma unroll
        for (int o = 16; o; o >>= 1) sm += __shfl_xor_sync(0xffffffffu, sm, o);
        if (lane == 0) s_inv = 1.0f / sm;
    }
    __syncthreads();
    const float inv = s_inv;

    float acc0 = 0.f, acc1 = 0.f, acc2 = 0.f, acc3 = 0.f;
    const float* vbase = qkv + (size_t)(b * SEQT) * 12288 + 8192 + hoff;
    for (int j = 0; j < nj; j++) {
        const float p = probs[j];
        const float* vrow = vbase + (size_t)j * 12288;
        acc0 = fmaf(p, vrow[tid      ], acc0);
        acc1 = fmaf(p, vrow[tid + 256], acc1);
        acc2 = fmaf(p, vrow[tid + 512], acc2);
        acc3 = fmaf(p, vrow[tid + 768], acc3);
    }
    float* orow = out + ((size_t)(b * SEQT + i)) * INNERC + hoff;
    orow[tid      ] = acc0 * inv;
    orow[tid + 256] = acc1 * inv;
    orow[tid + 512] = acc2 * inv;
    orow[tid + 768] = acc3 * inv;
}

// ---------------------------------------------------------------------------
// Launcher
// ---------------------------------------------------------------------------
extern "C" void kernel_launch(void* const* d_in, const int* in_sizes, int n_in,
                              void* d_out, int out_size)
{
    const float* features    = (const float*)d_in[0];
    const float* mnorm_w     = (const float*)d_in[1];
    const float* mnorm_b     = (const float*)d_in[2];
    const float* in_proj_w   = (const float*)d_in[3];
    const float* conv_w      = (const float*)d_in[4];
    const float* conv_b      = (const float*)d_in[5];
    const float* x_proj_w    = (const float*)d_in[6];
    const float* dt_proj_w   = (const float*)d_in[7];
    const float* dt_proj_b   = (const float*)d_in[8];
    const float* A_log       = (const float*)d_in[9];
    const float* D_skip      = (const float*)d_in[10];
    const float* mamba_out_w = (const float*)d_in[11];
    const float* ln1_w       = (const float*)d_in[12];
    const float* ln1_b       = (const float*)d_in[13];
    const float* qkv_w       = (const float*)d_in[14];
    const float* attn_out_w  = (const float*)d_in[15];
    const float* attn_out_b  = (const float*)d_in[16];
    const float* ln2_w       = (const float*)d_in[17];
    const float* ln2_b       = (const float*)d_in[18];
    const float* ffn_w1      = (const float*)d_in[19];
    const float* ffn_b1      = (const float*)d_in[20];
    const float* ffn_w2      = (const float*)d_in[21];
    const float* ffn_b2      = (const float*)d_in[22];

    float *p_norm, *p_xz, *p_xc, *p_xdbl, *p_dt, *p_y, *p_qkv, *p_attn, *p_ffn;
    cudaGetSymbolAddress((void**)&p_norm, g_norm);
    cudaGetSymbolAddress((void**)&p_xz,   g_xz);
    cudaGetSymbolAddress((void**)&p_xc,   g_xc);
    cudaGetSymbolAddress((void**)&p_xdbl, g_xdbl);
    cudaGetSymbolAddress((void**)&p_dt,   g_dt);
    cudaGetSymbolAddress((void**)&p_y,    g_y);
    cudaGetSymbolAddress((void**)&p_qkv,  g_qkv);
    cudaGetSymbolAddress((void**)&p_attn, g_attn);
    cudaGetSymbolAddress((void**)&p_ffn,  g_ffn);

    float* X = (float*)d_out;   // residual stream lives in d_out
    cudaMemcpyAsync(X, features, sizeof(float) * (size_t)MTOT * DIMC,
                    cudaMemcpyDeviceToDevice);

    for (int i = 0; i < DEPTHC; i++) {
        // ---- Mamba block ----
        ln_kernel<<<MTOT, 256>>>(X, mnorm_w + i * DIMC, mnorm_b + i * DIMC, p_norm);
        gemm_nt<0><<<dim3(32, 10), 256>>>(p_norm, DIMC,
                                          in_proj_w + (size_t)i * 4096 * DIMC, DIMC,
                                          nullptr, p_xz, 4096, MTOT, 4096, DIMC);
        conv_kernel<<<dim3(MTOT, 8), 256>>>(p_xz, conv_w + (size_t)i * DINC * 4,
                                            conv_b + i * DINC, p_xc);
        gemm_xproj<<<75, 256>>>(p_xc, x_proj_w + (size_t)i * XDBLC * DINC, p_xdbl);
        gemm_nt<5><<<dim3(16, 10), 256>>>(p_xdbl, XDBLC,
                                          dt_proj_w + (size_t)i * DINC * DTRANK, DTRANK,
                                          dt_proj_b + i * DINC, p_dt, DINC,
                                          MTOT, DINC, DTRANK);
        scan_kernel<<<dim3(128, BATCH), 256>>>(p_dt, p_xc, p_xdbl,
                                               A_log + (size_t)i * DINC * DSTATE,
                                               D_skip + i * DINC, p_xz, p_y);
        gemm_nt<3><<<dim3(8, 10), 256>>>(p_y, DINC,
                                         mamba_out_w + (size_t)i * DIMC * DINC, DINC,
                                         nullptr, X, DIMC, MTOT, DIMC, DINC);

        // ---- Attention block ----
        ln_kernel<<<MTOT, 256>>>(X, ln1_w + i * DIMC, ln1_b + i * DIMC, p_norm);
        gemm_nt<0><<<dim3(96, 10), 256>>>(p_norm, DIMC,
                                          qkv_w + (size_t)i * 3 * INNERC * DIMC, DIMC,
                                          nullptr, p_qkv, 3 * INNERC,
                                          MTOT, 3 * INNERC, DIMC);
        attn_kernel<<<dim3(SEQT, 4, BATCH), 256>>>(p_qkv, p_attn);
        gemm_nt<4><<<dim3(8, 10), 256>>>(p_attn, INNERC,
                                         attn_out_w + (size_t)i * DIMC * INNERC, INNERC,
                                         attn_out_b + i * DIMC, X, DIMC,
                                         MTOT, DIMC, INNERC);

        // ---- FFN block ----
        ln_kernel<<<MTOT, 256>>>(X, ln2_w + i * DIMC, ln2_b + i * DIMC, p_norm);
        gemm_nt<2><<<dim3(32, 10), 256>>>(p_norm, DIMC,
                                          ffn_w1 + (size_t)i * MLPC * DIMC, DIMC,
                                          ffn_b1 + i * MLPC, p_ffn, MLPC,
                                          MTOT, MLPC, DIMC);
        gemm_nt<3><<<dim3(8, 10), 256>>>(p_ffn, MLPC,
                                         ffn_w2 + (size_t)i * DIMC * MLPC, MLPC,
                                         ffn_b2 + i * DIMC, X, DIMC,
                                         MTOT, DIMC, MLPC);
    }
}

// round 2
// speedup vs baseline: 1.5748x; 1.5748x over previous
#include <cuda_runtime.h>
#include <math.h>
#include <stdint.h>

// ---------------------------------------------------------------------------
// Problem constants
// ---------------------------------------------------------------------------
#define BATCH   8
#define SEQT    150
#define MTOT    1200            // BATCH*SEQT
#define DIMC    1024
#define DINC    2048            // D_IN
#define DSTATE  16
#define DTRANK  64
#define XDBLC   96              // DT_RANK + 2*D_STATE
#define INNERC  4096            // HEADS * DIM_HEAD
#define MLPC    4096
#define DEPTHC  5

// ---------------------------------------------------------------------------
// Scratch (no allocations allowed -> __device__ globals)
// ---------------------------------------------------------------------------
__device__ float g_norm [MTOT * DIMC];
__device__ float g_xz   [MTOT * 2 * DINC];
__device__ float g_xc   [MTOT * DINC];
__device__ float g_xdbl [MTOT * XDBLC];
__device__ float g_dt   [MTOT * DINC];
__device__ float g_y    [MTOT * DINC];
__device__ float g_qkv  [MTOT * 3 * INNERC];
__device__ float g_attn [MTOT * INNERC];
__device__ float g_ffn  [MTOT * MLPC];

// ---------------------------------------------------------------------------
// Math helpers
// ---------------------------------------------------------------------------
__device__ __forceinline__ float geluf(float x) {
    return 0.5f * x * (1.0f + erff(x * 0.70710678118654752f));
}
__device__ __forceinline__ float softplusf(float x) {
    return fmaxf(x, 0.0f) + log1pf(__expf(-fabsf(x)));
}
__device__ __forceinline__ float siluf(float x) {
    return x / (1.0f + __expf(-x));
}
__device__ __forceinline__ float f2tf32f(float x) {
    uint32_t r;
    asm("cvt.rna.tf32.f32 %0, %1;" : "=r"(r) : "f"(x));
    return __uint_as_float(r);
}
__device__ __forceinline__ void mma_tf32(float c[4],
                                         uint32_t a0, uint32_t a1, uint32_t a2, uint32_t a3,
                                         uint32_t b0, uint32_t b1) {
    asm volatile(
        "mma.sync.aligned.m16n8k8.row.col.f32.tf32.tf32.f32 "
        "{%0,%1,%2,%3}, {%4,%5,%6,%7}, {%8,%9}, {%0,%1,%2,%3};"
        : "+f"(c[0]), "+f"(c[1]), "+f"(c[2]), "+f"(c[3])
        : "r"(a0), "r"(a1), "r"(a2), "r"(a3), "r"(b0), "r"(b1));
}

// ---------------------------------------------------------------------------
// Tensor-core NT GEMM (TF32): C[M,N] (+)= epi( A[M,K] * B[N,K]^T + bias )
// 128x128 tile, BK=16, 256 threads (8 warps: 4 along M x 2 along N),
// warp tile 32x64 = 2x8 atoms of m16n8k8. K % 16 == 0; row strides % 4 == 0.
// EPI: 0=store  1=+bias  2=gelu(+bias)  3=C+=acc(+bias)  4=C+=gelu(acc+bias)
//      5=softplus(acc+bias)
// ---------------------------------------------------------------------------
template <int EPI>
__global__ void __launch_bounds__(256)
gemm_tc(const float* __restrict__ A, int lda,
        const float* __restrict__ B, int ldb,
        const float* __restrict__ bias,
        float* __restrict__ C, int ldc,
        int M, int N, int K)
{
    __shared__ __align__(16) float As[16][136];
    __shared__ __align__(16) float Bs[16][136];

    const int m0   = blockIdx.y * 128;
    const int n0   = blockIdx.x * 128;
    const int tid  = threadIdx.x;
    const int lane = tid & 31;
    const int warp = tid >> 5;
    const int wm   = warp & 3;      // 0..3  (M offset 32*wm)
    const int wn   = warp >> 2;     // 0..1  (N offset 64*wn)
    const int ar   = lane >> 2;     // 0..7
    const int ac   = lane & 3;      // 0..3

    float acc[2][8][4];
#pragma unroll
    for (int i = 0; i < 2; i++)
#pragma unroll
        for (int j = 0; j < 8; j++)
#pragma unroll
            for (int r = 0; r < 4; r++) acc[i][j][r] = 0.0f;

    for (int k0 = 0; k0 < K; k0 += 16) {
#pragma unroll
        for (int r = 0; r < 2; r++) {
            const int idx = tid + r * 256;      // 0..511
            const int row = idx >> 2;           // 0..127
            const int kq  = (idx & 3) << 2;     // 0,4,8,12
            float4 va = make_float4(0.f, 0.f, 0.f, 0.f);
            if (m0 + row < M)
                va = *reinterpret_cast<const float4*>(&A[(size_t)(m0 + row) * lda + k0 + kq]);
            As[kq + 0][row] = f2tf32f(va.x); As[kq + 1][row] = f2tf32f(va.y);
            As[kq + 2][row] = f2tf32f(va.z); As[kq + 3][row] = f2tf32f(va.w);
            float4 vb = make_float4(0.f, 0.f, 0.f, 0.f);
            if (n0 + row < N)
                vb = *reinterpret_cast<const float4*>(&B[(size_t)(n0 + row) * ldb + k0 + kq]);
            Bs[kq + 0][row] = f2tf32f(vb.x); Bs[kq + 1][row] = f2tf32f(vb.y);
            Bs[kq + 2][row] = f2tf32f(vb.z); Bs[kq + 3][row] = f2tf32f(vb.w);
        }
        __syncthreads();

#pragma unroll
        for (int ks = 0; ks < 2; ks++) {
            const int kk = ks * 8;
            uint32_t a[2][4], b[8][2];
#pragma unroll
            for (int i = 0; i < 2; i++) {
                const int r = wm * 32 + i * 16 + ar;
                a[i][0] = __float_as_uint(As[kk + ac    ][r    ]);
                a[i][1] = __float_as_uint(As[kk + ac    ][r + 8]);
                a[i][2] = __float_as_uint(As[kk + ac + 4][r    ]);
                a[i][3] = __float_as_uint(As[kk + ac + 4][r + 8]);
            }
#pragma unroll
            for (int j = 0; j < 8; j++) {
                const int c = wn * 64 + j * 8 + ar;
                b[j][0] = __float_as_uint(Bs[kk + ac    ][c]);
                b[j][1] = __float_as_uint(Bs[kk + ac + 4][c]);
            }
#pragma unroll
            for (int i = 0; i < 2; i++)
#pragma unroll
                for (int j = 0; j < 8; j++)
                    mma_tf32(acc[i][j], a[i][0], a[i][1], a[i][2], a[i][3],
                             b[j][0], b[j][1]);
        }
        __syncthreads();
    }

    // Epilogue
#pragma unroll
    for (int i = 0; i < 2; i++) {
#pragma unroll
        for (int j = 0; j < 8; j++) {
            const int mb = m0 + wm * 32 + i * 16 + ar;
            const int nb = n0 + wn * 64 + j * 8 + ac * 2;
#pragma unroll
            for (int r2 = 0; r2 < 2; r2++) {
#pragma unroll
                for (int c2 = 0; c2 < 2; c2++) {
                    const int m = mb + r2 * 8;
                    const int n = nb + c2;
                    if (m >= M || n >= N) continue;
                    const size_t o = (size_t)m * ldc + n;
                    float v = acc[i][j][r2 * 2 + c2];
                    if (EPI == 0)      C[o] = v;
                    else if (EPI == 1) C[o] = v + bias[n];
                    else if (EPI == 2) C[o] = geluf(v + bias[n]);
                    else if (EPI == 3) C[o] = C[o] + v + (bias ? bias[n] : 0.0f);
                    else if (EPI == 4) C[o] = C[o] + geluf(v + bias[n]);
                    else if (EPI == 5) C[o] = softplusf(v + bias[n]);
                }
            }
        }
    }
}

// ---------------------------------------------------------------------------
// Skinny GEMM for x_proj: C[1200,96] = A[1200,2048] * B[96,2048]^T
// ---------------------------------------------------------------------------
__global__ void __launch_bounds__(256)
gemm_xproj(const float* __restrict__ A, const float* __restrict__ B,
           float* __restrict__ C)
{
    __shared__ float As[16][33];
    __shared__ float Bs[96][33];
    const int m0  = blockIdx.x * 16;
    const int tid = threadIdx.x;
    const int ml  = tid >> 4;           // 0..15
    const int nb  = (tid & 15) * 6;     // 0..90

    float acc[6] = {0.f, 0.f, 0.f, 0.f, 0.f, 0.f};

    for (int k0 = 0; k0 < 2048; k0 += 32) {
#pragma unroll
        for (int u = 0; u < 2; u++) {
            const int idx = tid + u * 256;
            const int r = idx >> 5, kk = idx & 31;
            As[r][kk] = A[(size_t)(m0 + r) * 2048 + k0 + kk];
        }
#pragma unroll
        for (int u = 0; u < 12; u++) {
            const int idx = tid + u * 256;
            const int r = idx >> 5, kk = idx & 31;
            Bs[r][kk] = B[(size_t)r * 2048 + k0 + kk];
        }
        __syncthreads();
#pragma unroll
        for (int kk = 0; kk < 32; kk++) {
            const float a = As[ml][kk];
#pragma unroll
            for (int j = 0; j < 6; j++)
                acc[j] = fmaf(a, Bs[nb + j][kk], acc[j]);
        }
        __syncthreads();
    }
#pragma unroll
    for (int j = 0; j < 6; j++)
        C[(size_t)(m0 + ml) * 96 + nb + j] = acc[j];
}

// ---------------------------------------------------------------------------
// LayerNorm: one block per row of 1024
// ---------------------------------------------------------------------------
__global__ void __launch_bounds__(256)
ln_kernel(const float* __restrict__ x, const float* __restrict__ w,
          const float* __restrict__ b, float* __restrict__ out)
{
    const int row = blockIdx.x;
    const int tid = threadIdx.x;
    const float* xr = x + (size_t)row * DIMC;
    __shared__ float red[8];

    float v[4];
    float s = 0.f;
#pragma unroll
    for (int u = 0; u < 4; u++) { v[u] = xr[tid + u * 256]; s += v[u]; }
#pragma unroll
    for (int o = 16; o; o >>= 1) s += __shfl_xor_sync(0xffffffffu, s, o);
    if ((tid & 31) == 0) red[tid >> 5] = s;
    __syncthreads();
    float tot = 0.f;
#pragma unroll
    for (int u = 0; u < 8; u++) tot += red[u];
    const float mu = tot * (1.0f / 1024.0f);

    float s2 = 0.f;
#pragma unroll
    for (int u = 0; u < 4; u++) { const float d = v[u] - mu; s2 += d * d; }
    __syncthreads();
#pragma unroll
    for (int o = 16; o; o >>= 1) s2 += __shfl_xor_sync(0xffffffffu, s2, o);
    if ((tid & 31) == 0) red[tid >> 5] = s2;
    __syncthreads();
    float tot2 = 0.f;
#pragma unroll
    for (int u = 0; u < 8; u++) tot2 += red[u];
    const float rstd = rsqrtf(tot2 * (1.0f / 1024.0f) + 1e-5f);

    float* orow = out + (size_t)row * DIMC;
#pragma unroll
    for (int u = 0; u < 4; u++) {
        const int c = tid + u * 256;
        orow[c] = (v[u] - mu) * rstd * w[c] + b[c];
    }
}

// ---------------------------------------------------------------------------
// Depthwise causal conv (width 4) + bias + silu
// ---------------------------------------------------------------------------
__global__ void __launch_bounds__(256)
conv_kernel(const float* __restrict__ xz, const float* __restrict__ cw,
            const float* __restrict__ cb, float* __restrict__ out)
{
    const int m = blockIdx.x;
    const int d = blockIdx.y * 256 + threadIdx.x;
    const int b = m / SEQT, t = m % SEQT;
    float acc = cb[d];
#pragma unroll
    for (int j = 0; j < 4; j++) {
        const int tt = t + j - 3;
        if (tt >= 0)
            acc = fmaf(cw[d * 4 + j], xz[((size_t)(b * SEQT + tt)) * 4096 + d], acc);
    }
    out[(size_t)m * DINC + d] = siluf(acc);
}

// ---------------------------------------------------------------------------
// Selective scan. Block = 16 d-lanes x 16 states, grid (128, B).
// ---------------------------------------------------------------------------
__global__ void __launch_bounds__(256)
scan_kernel(const float* __restrict__ dt, const float* __restrict__ xc,
            const float* __restrict__ xdbl, const float* __restrict__ A_log,
            const float* __restrict__ Dw, const float* __restrict__ xz,
            float* __restrict__ y)
{
    const int tid = threadIdx.x;
    const int dl = tid & 15;
    const int s  = tid >> 4;
    const int d  = blockIdx.x * 16 + dl;
    const int b  = blockIdx.y;

    const float a = -expf(A_log[d * 16 + s]);
    float h = 0.f;
    float Dv = (s == 0) ? Dw[d] : 0.f;

    __shared__ float red[16][17];

    for (int t = 0; t < SEQT; t++) {
        const size_t base = (size_t)(b * SEQT + t);
        const float dtv = dt[base * DINC + d];
        const float xcv = xc[base * DINC + d];
        const float Bv  = xdbl[base * XDBLC + 64 + s];
        const float Cv  = xdbl[base * XDBLC + 80 + s];
        h = __expf(dtv * a) * h + dtv * Bv * xcv;
        red[s][dl] = h * Cv;
        __syncthreads();
        if (s == 0) {
            float sum = 0.f;
#pragma unroll
            for (int ss = 0; ss < 16; ss++) sum += red[ss][dl];
            const float zv = xz[base * 4096 + 2048 + d];
            y[base * DINC + d] = (sum + Dv * xcv) * (zv / (1.0f + __expf(-zv)));
        }
        __syncthreads();
    }
}

// ---------------------------------------------------------------------------
// Causal attention, one block per (query row i, head, batch).
// ---------------------------------------------------------------------------
__global__ void __launch_bounds__(256)
attn_kernel(const float* __restrict__ qkv, float* __restrict__ out)
{
    const int i  = blockIdx.x;
    const int hh = blockIdx.y;
    const int b  = blockIdx.z;
    const int tid  = threadIdx.x;
    const int lane = tid & 31;
    const int w    = tid >> 5;

    __shared__ float qs[1024];
    __shared__ float probs[152];
    __shared__ float s_inv;

    const size_t hoff = (size_t)hh * 1024;
    const float* qrow = qkv + ((size_t)(b * SEQT + i)) * 12288 + hoff;
#pragma unroll
    for (int u = 0; u < 4; u++) qs[tid + u * 256] = qrow[tid + u * 256];
    __syncthreads();

    const int nj = i + 1;
    for (int j = w; j < nj; j += 8) {
        const float* krow = qkv + ((size_t)(b * SEQT + j)) * 12288 + 4096 + hoff;
        float sdot = 0.f;
        for (int u = lane; u < 1024; u += 32) sdot = fmaf(qs[u], krow[u], sdot);
#pragma unroll
        for (int o = 16; o; o >>= 1) sdot += __shfl_xor_sync(0xffffffffu, sdot, o);
        if (lane == 0) probs[j] = sdot * 0.03125f;
    }
    __syncthreads();

    if (w == 0) {
        float mx = -3.0e38f;
        for (int j = lane; j < nj; j += 32) mx = fmaxf(mx, probs[j]);
#pragma unroll
        for (int o = 16; o; o >>= 1) mx = fmaxf(mx, __shfl_xor_sync(0xffffffffu, mx, o));
        float sm = 0.f;
        for (int j = lane; j < nj; j += 32) {
            const float e = __expf(probs[j] - mx);
            probs[j] = e;
            sm += e;
        }
#pragma unroll
        for (int o = 16; o; o >>= 1) sm += __shfl_xor_sync(0xffffffffu, sm, o);
        if (lane == 0) s_inv = 1.0f / sm;
    }
    __syncthreads();
    const float inv = s_inv;

    float acc0 = 0.f, acc1 = 0.f, acc2 = 0.f, acc3 = 0.f;
    const float* vbase = qkv + (size_t)(b * SEQT) * 12288 + 8192 + hoff;
    for (int j = 0; j < nj; j++) {
        const float p = probs[j];
        const float* vrow = vbase + (size_t)j * 12288;
        acc0 = fmaf(p, vrow[tid      ], acc0);
        acc1 = fmaf(p, vrow[tid + 256], acc1);
        acc2 = fmaf(p, vrow[tid + 512], acc2);
        acc3 = fmaf(p, vrow[tid + 768], acc3);
    }
    float* orow = out + ((size_t)(b * SEQT + i)) * INNERC + hoff;
    orow[tid      ] = acc0 * inv;
    orow[tid + 256] = acc1 * inv;
    orow[tid + 512] = acc2 * inv;
    orow[tid + 768] = acc3 * inv;
}

// ---------------------------------------------------------------------------
// Launcher
// ---------------------------------------------------------------------------
extern "C" void kernel_launch(void* const* d_in, const int* in_sizes, int n_in,
                              void* d_out, int out_size)
{
    const float* features    = (const float*)d_in[0];
    const float* mnorm_w     = (const float*)d_in[1];
    const float* mnorm_b     = (const float*)d_in[2];
    const float* in_proj_w   = (const float*)d_in[3];
    const float* conv_w      = (const float*)d_in[4];
    const float* conv_b      = (const float*)d_in[5];
    const float* x_proj_w    = (const float*)d_in[6];
    const float* dt_proj_w   = (const float*)d_in[7];
    const float* dt_proj_b   = (const float*)d_in[8];
    const float* A_log       = (const float*)d_in[9];
    const float* D_skip      = (const float*)d_in[10];
    const float* mamba_out_w = (const float*)d_in[11];
    const float* ln1_w       = (const float*)d_in[12];
    const float* ln1_b       = (const float*)d_in[13];
    const float* qkv_w       = (const float*)d_in[14];
    const float* attn_out_w  = (const float*)d_in[15];
    const float* attn_out_b  = (const float*)d_in[16];
    const float* ln2_w       = (const float*)d_in[17];
    const float* ln2_b       = (const float*)d_in[18];
    const float* ffn_w1      = (const float*)d_in[19];
    const float* ffn_b1      = (const float*)d_in[20];
    const float* ffn_w2      = (const float*)d_in[21];
    const float* ffn_b2      = (const float*)d_in[22];

    float *p_norm, *p_xz, *p_xc, *p_xdbl, *p_dt, *p_y, *p_qkv, *p_attn, *p_ffn;
    cudaGetSymbolAddress((void**)&p_norm, g_norm);
    cudaGetSymbolAddress((void**)&p_xz,   g_xz);
    cudaGetSymbolAddress((void**)&p_xc,   g_xc);
    cudaGetSymbolAddress((void**)&p_xdbl, g_xdbl);
    cudaGetSymbolAddress((void**)&p_dt,   g_dt);
    cudaGetSymbolAddress((void**)&p_y,    g_y);
    cudaGetSymbolAddress((void**)&p_qkv,  g_qkv);
    cudaGetSymbolAddress((void**)&p_attn, g_attn);
    cudaGetSymbolAddress((void**)&p_ffn,  g_ffn);

    float* X = (float*)d_out;   // residual stream lives in d_out
    cudaMemcpyAsync(X, features, sizeof(float) * (size_t)MTOT * DIMC,
                    cudaMemcpyDeviceToDevice);

    for (int i = 0; i < DEPTHC; i++) {
        // ---- Mamba block ----
        ln_kernel<<<MTOT, 256>>>(X, mnorm_w + i * DIMC, mnorm_b + i * DIMC, p_norm);
        gemm_tc<0><<<dim3(32, 10), 256>>>(p_norm, DIMC,
                                          in_proj_w + (size_t)i * 4096 * DIMC, DIMC,
                                          nullptr, p_xz, 4096, MTOT, 4096, DIMC);
        conv_kernel<<<dim3(MTOT, 8), 256>>>(p_xz, conv_w + (size_t)i * DINC * 4,
                                            conv_b + i * DINC, p_xc);
        gemm_xproj<<<75, 256>>>(p_xc, x_proj_w + (size_t)i * XDBLC * DINC, p_xdbl);
        gemm_tc<5><<<dim3(16, 10), 256>>>(p_xdbl, XDBLC,
                                          dt_proj_w + (size_t)i * DINC * DTRANK, DTRANK,
                                          dt_proj_b + i * DINC, p_dt, DINC,
                                          MTOT, DINC, DTRANK);
        scan_kernel<<<dim3(128, BATCH), 256>>>(p_dt, p_xc, p_xdbl,
                                               A_log + (size_t)i * DINC * DSTATE,
                                               D_skip + i * DINC, p_xz, p_y);
        gemm_tc<3><<<dim3(8, 10), 256>>>(p_y, DINC,
                                         mamba_out_w + (size_t)i * DIMC * DINC, DINC,
                                         nullptr, X, DIMC, MTOT, DIMC, DINC);

        // ---- Attention block ----
        ln_kernel<<<MTOT, 256>>>(X, ln1_w + i * DIMC, ln1_b + i * DIMC, p_norm);
        gemm_tc<0><<<dim3(96, 10), 256>>>(p_norm, DIMC,
                                          qkv_w + (size_t)i * 3 * INNERC * DIMC, DIMC,
                                          nullptr, p_qkv, 3 * INNERC,
                                          MTOT, 3 * INNERC, DIMC);
        attn_kernel<<<dim3(SEQT, 4, BATCH), 256>>>(p_qkv, p_attn);
        gemm_tc<4><<<dim3(8, 10), 256>>>(p_attn, INNERC,
                                         attn_out_w + (size_t)i * DIMC * INNERC, INNERC,
                                         attn_out_b + i * DIMC, X, DIMC,
                                         MTOT, DIMC, INNERC);

        // ---- FFN block ----
        ln_kernel<<<MTOT, 256>>>(X, ln2_w + i * DIMC, ln2_b + i * DIMC, p_norm);
        gemm_tc<2><<<dim3(32, 10), 256>>>(p_norm, DIMC,
                                          ffn_w1 + (size_t)i * MLPC * DIMC, DIMC,
                                          ffn_b1 + i * MLPC, p_ffn, MLPC,
                                          MTOT, MLPC, DIMC);
        gemm_tc<3><<<dim3(8, 10), 256>>>(p_ffn, MLPC,
                                         ffn_w2 + (size_t)i * DIMC * MLPC, MLPC,
                                         ffn_b2 + i * DIMC, X, DIMC,
                                         MTOT, DIMC, MLPC);
    }
}

// round 3
// speedup vs baseline: 2.3929x; 1.5195x over previous
#include <cuda_runtime.h>
#include <math.h>
#include <stdint.h>

// ---------------------------------------------------------------------------
#define BATCH   8
#define SEQT    150
#define MTOT    1200
#define DIMC    1024
#define DINC    2048
#define DSTATE  16
#define DTRANK  64
#define XDBLC   96
#define INNERC  4096
#define MLPC    4096
#define DEPTHC  5

// ---------------------------------------------------------------------------
__device__ float g_norm [MTOT * DIMC];
__device__ float g_xz   [MTOT * 2 * DINC];
__device__ float g_xc   [MTOT * DINC];
__device__ float g_xdbl [MTOT * XDBLC];
__device__ float g_dt   [MTOT * DINC];
__device__ float g_y    [MTOT * DINC];
__device__ float g_qkv  [MTOT * 3 * INNERC];
__device__ float g_attn [MTOT * INNERC];
__device__ float g_ffn  [MTOT * MLPC];

// ---------------------------------------------------------------------------
__device__ __forceinline__ float geluf(float x) {
    return 0.5f * x * (1.0f + erff(x * 0.70710678118654752f));
}
__device__ __forceinline__ float softplusf(float x) {
    return fmaxf(x, 0.0f) + log1pf(__expf(-fabsf(x)));
}
__device__ __forceinline__ float siluf(float x) {
    return x / (1.0f + __expf(-x));
}
__device__ __forceinline__ float f2tf32f(float x) {
    uint32_t r;
    asm("cvt.rna.tf32.f32 %0, %1;" : "=r"(r) : "f"(x));
    return __uint_as_float(r);
}
__device__ __forceinline__ void mma_tf32(float c[4],
                                         uint32_t a0, uint32_t a1, uint32_t a2, uint32_t a3,
                                         uint32_t b0, uint32_t b1) {
    asm volatile(
        "mma.sync.aligned.m16n8k8.row.col.f32.tf32.tf32.f32 "
        "{%0,%1,%2,%3}, {%4,%5,%6,%7}, {%8,%9}, {%0,%1,%2,%3};"
        : "+f"(c[0]), "+f"(c[1]), "+f"(c[2]), "+f"(c[3])
        : "r"(a0), "r"(a1), "r"(a2), "r"(a3), "r"(b0), "r"(b1));
}

// ---------------------------------------------------------------------------
// Double-buffered TF32 tensor-core NT GEMM.
// C[M,N] (+)= epi( A[M,K] * B[N,K]^T + bias ),  BM x 128 tile, BK=16,
// 256 threads. BM=128: 8 warps as 4Mx2N, warp tile 32x64.
//             BM=64 : 8 warps as 2Mx4N, warp tile 32x32.
// EPI: 0=store 1=+bias 2=gelu(+bias) 3=C+=acc(+bias) 4=C+=gelu(acc+bias)
//      5=softplus(acc+bias)
// ---------------------------------------------------------------------------
template <int EPI, int BM>
__global__ void __launch_bounds__(256, 2)
gemm_tc(const float* __restrict__ A, int lda,
        const float* __restrict__ B, int ldb,
        const float* __restrict__ bias,
        float* __restrict__ C, int ldc,
        int M, int N, int K)
{
    constexpr int PA  = (BM == 128) ? 136 : 72;   // As pitch (8 mod 32 -> conflict-free frag loads)
    constexpr int ARP = (BM == 128) ? 2 : 1;       // A-fill float4s per thread
    constexpr int MI  = 2;
    constexpr int NJ  = (BM == 128) ? 8 : 4;

    __shared__ __align__(16) float As[2][16][PA];
    __shared__ __align__(16) float Bs[2][16][136];

    const int m0   = blockIdx.y * BM;
    const int n0   = blockIdx.x * 128;
    const int tid  = threadIdx.x;
    const int lane = tid & 31;
    const int warp = tid >> 5;
    const int wm   = (BM == 128) ? (warp & 3) : (warp & 1);
    const int wn   = (BM == 128) ? (warp >> 2) : (warp >> 1);
    const int ar   = lane >> 2;
    const int ac   = lane & 3;

    float acc[MI][NJ][4];
#pragma unroll
    for (int i = 0; i < MI; i++)
#pragma unroll
        for (int j = 0; j < NJ; j++)
#pragma unroll
            for (int r = 0; r < 4; r++) acc[i][j][r] = 0.0f;

    float4 sa[ARP], sb[2];

    auto load_stage = [&](int k0) {
#pragma unroll
        for (int r = 0; r < ARP; r++) {
            const int idx = tid + r * 256;
            const int row = idx >> 2;
            const int kq  = (idx & 3) << 2;
            sa[r] = (m0 + row < M)
                  ? *reinterpret_cast<const float4*>(&A[(size_t)(m0 + row) * lda + k0 + kq])
                  : make_float4(0.f, 0.f, 0.f, 0.f);
        }
#pragma unroll
        for (int r = 0; r < 2; r++) {
            const int idx = tid + r * 256;
            const int row = idx >> 2;
            const int kq  = (idx & 3) << 2;
            sb[r] = (n0 + row < N)
                  ? *reinterpret_cast<const float4*>(&B[(size_t)(n0 + row) * ldb + k0 + kq])
                  : make_float4(0.f, 0.f, 0.f, 0.f);
        }
    };
    auto store_stage = [&](int p) {
#pragma unroll
        for (int r = 0; r < ARP; r++) {
            const int idx = tid + r * 256;
            const int row = idx >> 2;
            const int kq  = (idx & 3) << 2;
            As[p][kq + 0][row] = f2tf32f(sa[r].x);
            As[p][kq + 1][row] = f2tf32f(sa[r].y);
            As[p][kq + 2][row] = f2tf32f(sa[r].z);
            As[p][kq + 3][row] = f2tf32f(sa[r].w);
        }
#pragma unroll
        for (int r = 0; r < 2; r++) {
            const int idx = tid + r * 256;
            const int row = idx >> 2;
            const int kq  = (idx & 3) << 2;
            Bs[p][kq + 0][row] = f2tf32f(sb[r].x);
            Bs[p][kq + 1][row] = f2tf32f(sb[r].y);
            Bs[p][kq + 2][row] = f2tf32f(sb[r].z);
            Bs[p][kq + 3][row] = f2tf32f(sb[r].w);
        }
    };

    const int NIT = K >> 4;
    load_stage(0);
    store_stage(0);
    __syncthreads();

    for (int it = 0; it < NIT; it++) {
        const int p = it & 1;
        if (it + 1 < NIT) load_stage((it + 1) << 4);

#pragma unroll
        for (int ks = 0; ks < 2; ks++) {
            const int kk = ks * 8;
            uint32_t af[MI][4], bf[NJ][2];
#pragma unroll
            for (int i = 0; i < MI; i++) {
                const int r = wm * 32 + i * 16 + ar;
                af[i][0] = __float_as_uint(As[p][kk + ac    ][r    ]);
                af[i][1] = __float_as_uint(As[p][kk + ac    ][r + 8]);
                af[i][2] = __float_as_uint(As[p][kk + ac + 4][r    ]);
                af[i][3] = __float_as_uint(As[p][kk + ac + 4][r + 8]);
            }
#pragma unroll
            for (int j = 0; j < NJ; j++) {
                const int c = wn * (8 * NJ) + j * 8 + ar;
                bf[j][0] = __float_as_uint(Bs[p][kk + ac    ][c]);
                bf[j][1] = __float_as_uint(Bs[p][kk + ac + 4][c]);
            }
#pragma unroll
            for (int i = 0; i < MI; i++)
#pragma unroll
                for (int j = 0; j < NJ; j++)
                    mma_tf32(acc[i][j], af[i][0], af[i][1], af[i][2], af[i][3],
                             bf[j][0], bf[j][1]);
        }

        if (it + 1 < NIT) store_stage(p ^ 1);
        __syncthreads();
    }

#pragma unroll
    for (int i = 0; i < MI; i++) {
#pragma unroll
        for (int j = 0; j < NJ; j++) {
            const int mb = m0 + wm * 32 + i * 16 + ar;
            const int nb = n0 + wn * (8 * NJ) + j * 8 + ac * 2;
#pragma unroll
            for (int r2 = 0; r2 < 2; r2++) {
#pragma unroll
                for (int c2 = 0; c2 < 2; c2++) {
                    const int m = mb + r2 * 8;
                    const int n = nb + c2;
                    if (m >= M || n >= N) continue;
                    const size_t o = (size_t)m * ldc + n;
                    float v = acc[i][j][r2 * 2 + c2];
                    if (EPI == 0)      C[o] = v;
                    else if (EPI == 1) C[o] = v + bias[n];
                    else if (EPI == 2) C[o] = geluf(v + bias[n]);
                    else if (EPI == 3) C[o] = C[o] + v + (bias ? bias[n] : 0.0f);
                    else if (EPI == 4) C[o] = C[o] + geluf(v + bias[n]);
                    else if (EPI == 5) C[o] = softplusf(v + bias[n]);
                }
            }
        }
    }
}

// ---------------------------------------------------------------------------
// Skinny GEMM for x_proj: C[1200,96] = A[1200,2048] * B[96,2048]^T
// ---------------------------------------------------------------------------
__global__ void __launch_bounds__(256)
gemm_xproj(const float* __restrict__ A, const float* __restrict__ B,
           float* __restrict__ C)
{
    __shared__ float As[16][33];
    __shared__ float Bs[96][33];
    const int m0  = blockIdx.x * 16;
    const int tid = threadIdx.x;
    const int ml  = tid >> 4;
    const int nb  = (tid & 15) * 6;

    float acc[6] = {0.f, 0.f, 0.f, 0.f, 0.f, 0.f};

    for (int k0 = 0; k0 < 2048; k0 += 32) {
#pragma unroll
        for (int u = 0; u < 2; u++) {
            const int idx = tid + u * 256;
            const int r = idx >> 5, kk = idx & 31;
            As[r][kk] = A[(size_t)(m0 + r) * 2048 + k0 + kk];
        }
#pragma unroll
        for (int u = 0; u < 12; u++) {
            const int idx = tid + u * 256;
            const int r = idx >> 5, kk = idx & 31;
            Bs[r][kk] = B[(size_t)r * 2048 + k0 + kk];
        }
        __syncthreads();
#pragma unroll
        for (int kk = 0; kk < 32; kk++) {
            const float a = As[ml][kk];
#pragma unroll
            for (int j = 0; j < 6; j++)
                acc[j] = fmaf(a, Bs[nb + j][kk], acc[j]);
        }
        __syncthreads();
    }
#pragma unroll
    for (int j = 0; j < 6; j++)
        C[(size_t)(m0 + ml) * 96 + nb + j] = acc[j];
}

// ---------------------------------------------------------------------------
__global__ void __launch_bounds__(256)
ln_kernel(const float* __restrict__ x, const float* __restrict__ w,
          const float* __restrict__ b, float* __restrict__ out)
{
    const int row = blockIdx.x;
    const int tid = threadIdx.x;
    const float* xr = x + (size_t)row * DIMC;
    __shared__ float red[8];

    float v[4];
    float s = 0.f;
#pragma unroll
    for (int u = 0; u < 4; u++) { v[u] = xr[tid + u * 256]; s += v[u]; }
#pragma unroll
    for (int o = 16; o; o >>= 1) s += __shfl_xor_sync(0xffffffffu, s, o);
    if ((tid & 31) == 0) red[tid >> 5] = s;
    __syncthreads();
    float tot = 0.f;
#pragma unroll
    for (int u = 0; u < 8; u++) tot += red[u];
    const float mu = tot * (1.0f / 1024.0f);

    float s2 = 0.f;
#pragma unroll
    for (int u = 0; u < 4; u++) { const float d = v[u] - mu; s2 += d * d; }
    __syncthreads();
#pragma unroll
    for (int o = 16; o; o >>= 1) s2 += __shfl_xor_sync(0xffffffffu, s2, o);
    if ((tid & 31) == 0) red[tid >> 5] = s2;
    __syncthreads();
    float tot2 = 0.f;
#pragma unroll
    for (int u = 0; u < 8; u++) tot2 += red[u];
    const float rstd = rsqrtf(tot2 * (1.0f / 1024.0f) + 1e-5f);

    float* orow = out + (size_t)row * DIMC;
#pragma unroll
    for (int u = 0; u < 4; u++) {
        const int c = tid + u * 256;
        orow[c] = (v[u] - mu) * rstd * w[c] + b[c];
    }
}

// ---------------------------------------------------------------------------
__global__ void __launch_bounds__(256)
conv_kernel(const float* __restrict__ xz, const float* __restrict__ cw,
            const float* __restrict__ cb, float* __restrict__ out)
{
    const int m = blockIdx.x;
    const int d = blockIdx.y * 256 + threadIdx.x;
    const int b = m / SEQT, t = m % SEQT;
    float acc = cb[d];
#pragma unroll
    for (int j = 0; j < 4; j++) {
        const int tt = t + j - 3;
        if (tt >= 0)
            acc = fmaf(cw[d * 4 + j], xz[((size_t)(b * SEQT + tt)) * 4096 + d], acc);
    }
    out[(size_t)m * DINC + d] = siluf(acc);
}

// ---------------------------------------------------------------------------
__global__ void __launch_bounds__(256)
scan_kernel(const float* __restrict__ dt, const float* __restrict__ xc,
            const float* __restrict__ xdbl, const float* __restrict__ A_log,
            const float* __restrict__ Dw, const float* __restrict__ xz,
            float* __restrict__ y)
{
    const int tid = threadIdx.x;
    const int dl = tid & 15;
    const int s  = tid >> 4;
    const int d  = blockIdx.x * 16 + dl;
    const int b  = blockIdx.y;

    const float a = -expf(A_log[d * 16 + s]);
    float h = 0.f;
    float Dv = (s == 0) ? Dw[d] : 0.f;

    __shared__ float red[16][17];

    for (int t = 0; t < SEQT; t++) {
        const size_t base = (size_t)(b * SEQT + t);
        const float dtv = dt[base * DINC + d];
        const float xcv = xc[base * DINC + d];
        const float Bv  = xdbl[base * XDBLC + 64 + s];
        const float Cv  = xdbl[base * XDBLC + 80 + s];
        h = __expf(dtv * a) * h + dtv * Bv * xcv;
        red[s][dl] = h * Cv;
        __syncthreads();
        if (s == 0) {
            float sum = 0.f;
#pragma unroll
            for (int ss = 0; ss < 16; ss++) sum += red[ss][dl];
            const float zv = xz[base * 4096 + 2048 + d];
            y[base * DINC + d] = (sum + Dv * xcv) * (zv / (1.0f + __expf(-zv)));
        }
        __syncthreads();
    }
}

// ---------------------------------------------------------------------------
// Query-tiled causal attention. Block = (qtile of 16, head, batch).
// Pass B: scores via smem-staged K rows (rounds of 4, double-buffered).
// Pass C: softmax in smem. Pass D: PV with V kept entirely in registers
// (thread's 4 output cols == the 4 V floats it loads).
// ---------------------------------------------------------------------------
#define QT 16
__global__ void __launch_bounds__(256)
attn_tile_kernel(const float* __restrict__ qkv, float* __restrict__ out)
{
    const int qt = blockIdx.x;
    const int h  = blockIdx.y;
    const int b  = blockIdx.z;
    const int i0 = qt * QT;
    const int tid  = threadIdx.x;
    const int qi   = tid >> 4;        // 0..15 query within tile
    const int seg  = tid & 15;        // 64-float segment of the dot
    const int jmax = min(i0 + QT, SEQT);

    __shared__ __align__(16) float ks[2][4][16 * 68];  // pitch-68 seg blocks
    __shared__ float S[QT][152];
    __shared__ float sinv[QT];

    const size_t base_bh = (size_t)(b * SEQT) * 12288 + (size_t)h * 1024;
    const int sts_off = (tid >> 4) * 68 + ((tid * 4) & 63);

    // ---- load q tile into registers (clamp invalid rows) ----
    float4 qv[16];
    {
        const int row = min(i0 + qi, SEQT - 1);
        const float* qrow = qkv + (size_t)(b * SEQT + row) * 12288 + (size_t)h * 1024 + seg * 64;
#pragma unroll
        for (int u = 0; u < 16; u++)
            qv[u] = *reinterpret_cast<const float4*>(&qrow[u * 4]);
    }

    // ---- Pass B: scores ----
    const int rounds = (jmax + 3) >> 2;
    float4 st[4];
#pragma unroll
    for (int u = 0; u < 4; u++)
        st[u] = (u < jmax)
              ? *reinterpret_cast<const float4*>(qkv + base_bh + (size_t)u * 12288 + 4096 + tid * 4)
              : make_float4(0.f, 0.f, 0.f, 0.f);
#pragma unroll
    for (int u = 0; u < 4; u++)
        *reinterpret_cast<float4*>(&ks[0][u][sts_off]) = st[u];
    __syncthreads();

    for (int r = 0; r < rounds; r++) {
        const int p = r & 1;
        if (r + 1 < rounds) {
#pragma unroll
            for (int u = 0; u < 4; u++) {
                const int j = (r + 1) * 4 + u;
                st[u] = (j < jmax)
                      ? *reinterpret_cast<const float4*>(qkv + base_bh + (size_t)j * 12288 + 4096 + tid * 4)
                      : make_float4(0.f, 0.f, 0.f, 0.f);
            }
        }
#pragma unroll
        for (int u = 0; u < 4; u++) {
            const int j = r * 4 + u;
            if (j < jmax) {
                const float* kp = &ks[p][u][seg * 68];
                float part = 0.f;
#pragma unroll
                for (int e = 0; e < 16; e++) {
                    const float4 k4 = *reinterpret_cast<const float4*>(&kp[e * 4]);
                    part = fmaf(qv[e].x, k4.x, part);
                    part = fmaf(qv[e].y, k4.y, part);
                    part = fmaf(qv[e].z, k4.z, part);
                    part = fmaf(qv[e].w, k4.w, part);
                }
                part += __shfl_xor_sync(0xffffffffu, part, 8);
                part += __shfl_xor_sync(0xffffffffu, part, 4);
                part += __shfl_xor_sync(0xffffffffu, part, 2);
                part += __shfl_xor_sync(0xffffffffu, part, 1);
                if (seg == 0)
                    S[qi][j] = (j <= i0 + qi) ? part * 0.03125f : -1e30f;
            }
        }
        if (r + 1 < rounds) {
#pragma unroll
            for (int u = 0; u < 4; u++)
                *reinterpret_cast<float4*>(&ks[p ^ 1][u][sts_off]) = st[u];
        }
        __syncthreads();
    }

    // ---- Pass C: softmax over valid j ----
    {
        const int w = tid >> 5, lane = tid & 31;
        for (int qq = w; qq < QT; qq += 8) {
            float m = -3.0e38f;
            for (int j = lane; j < jmax; j += 32) m = fmaxf(m, S[qq][j]);
#pragma unroll
            for (int o = 16; o; o >>= 1) m = fmaxf(m, __shfl_xor_sync(0xffffffffu, m, o));
            float sm = 0.f;
            for (int j = lane; j < jmax; j += 32) {
                const float e = __expf(S[qq][j] - m);
                S[qq][j] = e;
                sm += e;
            }
#pragma unroll
            for (int o = 16; o; o >>= 1) sm += __shfl_xor_sync(0xffffffffu, sm, o);
            if (lane == 0) sinv[qq] = 1.0f / sm;
        }
    }
    __syncthreads();

    // ---- Pass D: PV, V in registers ----
    float4 acc4[QT];
#pragma unroll
    for (int q = 0; q < QT; q++) acc4[q] = make_float4(0.f, 0.f, 0.f, 0.f);

    const float* vbase = qkv + base_bh + 8192 + tid * 4;
    for (int j0 = 0; j0 < jmax; j0 += 4) {
        float4 vv[4];
#pragma unroll
        for (int u = 0; u < 4; u++) {
            const int j = j0 + u;
            vv[u] = (j < jmax) ? *reinterpret_cast<const float4*>(vbase + (size_t)j * 12288)
                               : make_float4(0.f, 0.f, 0.f, 0.f);
        }
#pragma unroll
        for (int u = 0; u < 4; u++) {
            const int j = j0 + u;
            if (j < jmax) {
#pragma unroll
                for (int q = 0; q < QT; q++) {
                    const float pbc = S[q][j];
                    acc4[q].x = fmaf(pbc, vv[u].x, acc4[q].x);
                    acc4[q].y = fmaf(pbc, vv[u].y, acc4[q].y);
                    acc4[q].z = fmaf(pbc, vv[u].z, acc4[q].z);
                    acc4[q].w = fmaf(pbc, vv[u].w, acc4[q].w);
                }
            }
        }
    }

#pragma unroll
    for (int q = 0; q < QT; q++) {
        const int rowq = i0 + q;
        if (rowq < SEQT) {
            const float inv = sinv[q];
            float4 o;
            o.x = acc4[q].x * inv; o.y = acc4[q].y * inv;
            o.z = acc4[q].z * inv; o.w = acc4[q].w * inv;
            *reinterpret_cast<float4*>(out + (size_t)(b * SEQT + rowq) * INNERC
                                       + (size_t)h * 1024 + tid * 4) = o;
        }
    }
}

// ---------------------------------------------------------------------------
extern "C" void kernel_launch(void* const* d_in, const int* in_sizes, int n_in,
                              void* d_out, int out_size)
{
    const float* features    = (const float*)d_in[0];
    const float* mnorm_w     = (const float*)d_in[1];
    const float* mnorm_b     = (const float*)d_in[2];
    const float* in_proj_w   = (const float*)d_in[3];
    const float* conv_w      = (const float*)d_in[4];
    const float* conv_b      = (const float*)d_in[5];
    const float* x_proj_w    = (const float*)d_in[6];
    const float* dt_proj_w   = (const float*)d_in[7];
    const float* dt_proj_b   = (const float*)d_in[8];
    const float* A_log       = (const float*)d_in[9];
    const float* D_skip      = (const float*)d_in[10];
    const float* mamba_out_w = (const float*)d_in[11];
    const float* ln1_w       = (const float*)d_in[12];
    const float* ln1_b       = (const float*)d_in[13];
    const float* qkv_w       = (const float*)d_in[14];
    const float* attn_out_w  = (const float*)d_in[15];
    const float* attn_out_b  = (const float*)d_in[16];
    const float* ln2_w       = (const float*)d_in[17];
    const float* ln2_b       = (const float*)d_in[18];
    const float* ffn_w1      = (const float*)d_in[19];
    const float* ffn_b1      = (const float*)d_in[20];
    const float* ffn_w2      = (const float*)d_in[21];
    const float* ffn_b2      = (const float*)d_in[22];

    float *p_norm, *p_xz, *p_xc, *p_xdbl, *p_dt, *p_y, *p_qkv, *p_attn, *p_ffn;
    cudaGetSymbolAddress((void**)&p_norm, g_norm);
    cudaGetSymbolAddress((void**)&p_xz,   g_xz);
    cudaGetSymbolAddress((void**)&p_xc,   g_xc);
    cudaGetSymbolAddress((void**)&p_xdbl, g_xdbl);
    cudaGetSymbolAddress((void**)&p_dt,   g_dt);
    cudaGetSymbolAddress((void**)&p_y,    g_y);
    cudaGetSymbolAddress((void**)&p_qkv,  g_qkv);
    cudaGetSymbolAddress((void**)&p_attn, g_attn);
    cudaGetSymbolAddress((void**)&p_ffn,  g_ffn);

    float* X = (float*)d_out;
    cudaMemcpyAsync(X, features, sizeof(float) * (size_t)MTOT * DIMC,
                    cudaMemcpyDeviceToDevice);

    for (int i = 0; i < DEPTHC; i++) {
        // ---- Mamba ----
        ln_kernel<<<MTOT, 256>>>(X, mnorm_w + i * DIMC, mnorm_b + i * DIMC, p_norm);
        gemm_tc<0, 128><<<dim3(32, 10), 256>>>(p_norm, DIMC,
                                               in_proj_w + (size_t)i * 4096 * DIMC, DIMC,
                                               nullptr, p_xz, 4096, MTOT, 4096, DIMC);
        conv_kernel<<<dim3(MTOT, 8), 256>>>(p_xz, conv_w + (size_t)i * DINC * 4,
                                            conv_b + i * DINC, p_xc);
        gemm_xproj<<<75, 256>>>(p_xc, x_proj_w + (size_t)i * XDBLC * DINC, p_xdbl);
        gemm_tc<5, 128><<<dim3(16, 10), 256>>>(p_xdbl, XDBLC,
                                               dt_proj_w + (size_t)i * DINC * DTRANK, DTRANK,
                                               dt_proj_b + i * DINC, p_dt, DINC,
                                               MTOT, DINC, DTRANK);
        scan_kernel<<<dim3(128, BATCH), 256>>>(p_dt, p_xc, p_xdbl,
                                               A_log + (size_t)i * DINC * DSTATE,
                                               D_skip + i * DINC, p_xz, p_y);
        gemm_tc<3, 64><<<dim3(8, 19), 256>>>(p_y, DINC,
                                             mamba_out_w + (size_t)i * DIMC * DINC, DINC,
                                             nullptr, X, DIMC, MTOT, DIMC, DINC);

        // ---- Attention ----
        ln_kernel<<<MTOT, 256>>>(X, ln1_w + i * DIMC, ln1_b + i * DIMC, p_norm);
        gemm_tc<0, 128><<<dim3(96, 10), 256>>>(p_norm, DIMC,
                                               qkv_w + (size_t)i * 3 * INNERC * DIMC, DIMC,
                                               nullptr, p_qkv, 3 * INNERC,
                                               MTOT, 3 * INNERC, DIMC);
        attn_tile_kernel<<<dim3(10, 4, BATCH), 256>>>(p_qkv, p_attn);
        gemm_tc<4, 64><<<dim3(8, 19), 256>>>(p_attn, INNERC,
                                             attn_out_w + (size_t)i * DIMC * INNERC, INNERC,
                                             attn_out_b + i * DIMC, X, DIMC,
                                             MTOT, DIMC, INNERC);

        // ---- FFN ----
        ln_kernel<<<MTOT, 256>>>(X, ln2_w + i * DIMC, ln2_b + i * DIMC, p_norm);
        gemm_tc<2, 128><<<dim3(32, 10), 256>>>(p_norm, DIMC,
                                               ffn_w1 + (size_t)i * MLPC * DIMC, DIMC,
                                               ffn_b1 + i * MLPC, p_ffn, MLPC,
                                               MTOT, MLPC, DIMC);
        gemm_tc<3, 64><<<dim3(8, 19), 256>>>(p_ffn, MLPC,
                                             ffn_w2 + (size_t)i * DIMC * MLPC, MLPC,
                                             ffn_b2 + i * DIMC, X, DIMC,
                                             MTOT, DIMC, MLPC);
    }
}

// round 4
// speedup vs baseline: 3.4486x; 1.4412x over previous
#include <cuda_runtime.h>
#include <math.h>
#include <stdint.h>

// ---------------------------------------------------------------------------
#define BATCH   8
#define SEQT    150
#define MTOT    1200
#define DIMC    1024
#define DINC    2048
#define DSTATE  16
#define DTRANK  64
#define XDBLC   96
#define INNERC  4096
#define MLPC    4096
#define DEPTHC  5
#define XKS     8          // split-K factor for x_proj

// ---------------------------------------------------------------------------
__device__ float g_norm [MTOT * DIMC];
__device__ float g_xz   [MTOT * 2 * DINC];
__device__ float g_xc   [MTOT * DINC];
__device__ float g_xdbl [MTOT * XDBLC];
__device__ float g_xpart[XKS * MTOT * XDBLC];
__device__ float g_dt   [MTOT * DINC];
__device__ float g_y    [MTOT * DINC];
__device__ float g_qkv  [MTOT * 3 * INNERC];
__device__ float g_attn [MTOT * INNERC];
__device__ float g_ffn  [MTOT * MLPC];

// ---------------------------------------------------------------------------
__device__ __forceinline__ float geluf(float x) {
    return 0.5f * x * (1.0f + erff(x * 0.70710678118654752f));
}
__device__ __forceinline__ float softplusf(float x) {
    return fmaxf(x, 0.0f) + log1pf(__expf(-fabsf(x)));
}
__device__ __forceinline__ float siluf(float x) {
    return x / (1.0f + __expf(-x));
}
__device__ __forceinline__ uint32_t ld_tf32(const float* p) {
    uint32_t r;
    asm("cvt.rna.tf32.f32 %0, %1;" : "=r"(r) : "f"(*p));
    return r;
}
__device__ __forceinline__ void mma_tf32(float c[4],
                                         uint32_t a0, uint32_t a1, uint32_t a2, uint32_t a3,
                                         uint32_t b0, uint32_t b1) {
    asm volatile(
        "mma.sync.aligned.m16n8k8.row.col.f32.tf32.tf32.f32 "
        "{%0,%1,%2,%3}, {%4,%5,%6,%7}, {%8,%9}, {%0,%1,%2,%3};"
        : "+f"(c[0]), "+f"(c[1]), "+f"(c[2]), "+f"(c[3])
        : "r"(a0), "r"(a1), "r"(a2), "r"(a3), "r"(b0), "r"(b1));
}
__device__ __forceinline__ void cp16(uint32_t dst, const float* src, int sz) {
    asm volatile("cp.async.cg.shared.global [%0], [%1], 16, %2;"
                 :: "r"(dst), "l"(src), "r"(sz));
}

// ---------------------------------------------------------------------------
// 4-stage cp.async TF32 tensor-core NT GEMM.
// C[M,N] (+)= epi( A[M,K] * B[N,K]^T + bias ),  BM x 128 tile, BK=16,
// 256 threads. BM=128: warps 4Mx2N (warp tile 32x64).
//              BM=64 : warps 2Mx4N (warp tile 32x32).
// smem rows pitch 20 floats -> (20r+k) mod 32 bijective over frag lanes.
// tf32 conversion (cvt.rna) at fragment load => numerics identical to R3.
// EPI: 0=store 1=+bias 2=gelu(+bias) 3=C+=acc(+bias) 4=C+=gelu(acc+bias)
//      5=softplus(acc+bias)
// ---------------------------------------------------------------------------
template <int EPI, int BM>
__global__ void __launch_bounds__(256, 2)
gemm_tc(const float* __restrict__ A, int lda,
        const float* __restrict__ B, int ldb,
        const float* __restrict__ bias,
        float* __restrict__ C, int ldc,
        int M, int N, int K)
{
    constexpr int PAD = 20;
    constexpr int MI  = 2;
    constexpr int NJ  = (BM == 128) ? 8 : 4;
    constexpr int ARQ = BM / 64;            // A cp.async quads per thread

    extern __shared__ float smem[];
    float* sA = smem;                        // [4][BM][PAD]
    float* sB = smem + 4 * BM * PAD;         // [4][128][PAD]

    const int m0   = blockIdx.y * BM;
    const int n0   = blockIdx.x * 128;
    const int tid  = threadIdx.x;
    const int lane = tid & 31;
    const int warp = tid >> 5;
    const int wm   = (BM == 128) ? (warp & 3) : (warp & 1);
    const int wn   = (BM == 128) ? (warp >> 2) : (warp >> 1);
    const int ar   = lane >> 2;
    const int ac   = lane & 3;

    const int NIT = K >> 4;

    float acc[MI][NJ][4];
#pragma unroll
    for (int i = 0; i < MI; i++)
#pragma unroll
        for (int j = 0; j < NJ; j++)
#pragma unroll
            for (int r = 0; r < 4; r++) acc[i][j][r] = 0.0f;

    auto issue = [&](int s, int k0, bool real) {
        if (real) {
#pragma unroll
            for (int r = 0; r < ARQ; r++) {
                const int idx = tid + r * 256;
                const int row = idx >> 2;
                const int kq  = (idx & 3) << 2;
                const float* src = &A[(size_t)(m0 + row) * lda + k0 + kq];
                uint32_t dst = (uint32_t)__cvta_generic_to_shared(
                    &sA[(s * BM + row) * PAD + kq]);
                cp16(dst, src, (m0 + row < M) ? 16 : 0);
            }
#pragma unroll
            for (int r = 0; r < 2; r++) {
                const int idx = tid + r * 256;
                const int row = idx >> 2;
                const int kq  = (idx & 3) << 2;
                const float* src = &B[(size_t)(n0 + row) * ldb + k0 + kq];
                uint32_t dst = (uint32_t)__cvta_generic_to_shared(
                    &sB[(s * 128 + row) * PAD + kq]);
                cp16(dst, src, (n0 + row < N) ? 16 : 0);
            }
        }
        asm volatile("cp.async.commit_group;");
    };

    issue(0, 0, true);
    issue(1, 16, 1 < NIT);
    issue(2, 32, 2 < NIT);

    for (int it = 0; it < NIT; it++) {
        const int p = it & 3;
        asm volatile("cp.async.wait_group 2;");
        __syncthreads();
        issue((it + 3) & 3, (it + 3) << 4, (it + 3) < NIT);

        const float* pa = &sA[p * BM * PAD];
        const float* pb = &sB[p * 128 * PAD];
#pragma unroll
        for (int ks = 0; ks < 2; ks++) {
            const int kk = ks * 8;
            uint32_t af[MI][4], bf[NJ][2];
#pragma unroll
            for (int i = 0; i < MI; i++) {
                const int r = wm * 32 + i * 16 + ar;
                af[i][0] = ld_tf32(&pa[(r    ) * PAD + kk + ac    ]);
                af[i][1] = ld_tf32(&pa[(r + 8) * PAD + kk + ac    ]);
                af[i][2] = ld_tf32(&pa[(r    ) * PAD + kk + ac + 4]);
                af[i][3] = ld_tf32(&pa[(r + 8) * PAD + kk + ac + 4]);
            }
#pragma unroll
            for (int j = 0; j < NJ; j++) {
                const int c = wn * (8 * NJ) + j * 8 + ar;
                bf[j][0] = ld_tf32(&pb[c * PAD + kk + ac    ]);
                bf[j][1] = ld_tf32(&pb[c * PAD + kk + ac + 4]);
            }
#pragma unroll
            for (int i = 0; i < MI; i++)
#pragma unroll
                for (int j = 0; j < NJ; j++)
                    mma_tf32(acc[i][j], af[i][0], af[i][1], af[i][2], af[i][3],
                             bf[j][0], bf[j][1]);
        }
        __syncthreads();
    }

#pragma unroll
    for (int i = 0; i < MI; i++) {
#pragma unroll
        for (int j = 0; j < NJ; j++) {
            const int mb = m0 + wm * 32 + i * 16 + ar;
            const int nb = n0 + wn * (8 * NJ) + j * 8 + ac * 2;
#pragma unroll
            for (int r2 = 0; r2 < 2; r2++) {
#pragma unroll
                for (int c2 = 0; c2 < 2; c2++) {
                    const int m = mb + r2 * 8;
                    const int n = nb + c2;
                    if (m >= M || n >= N) continue;
                    const size_t o = (size_t)m * ldc + n;
                    float v = acc[i][j][r2 * 2 + c2];
                    if (EPI == 0)      C[o] = v;
                    else if (EPI == 1) C[o] = v + bias[n];
                    else if (EPI == 2) C[o] = geluf(v + bias[n]);
                    else if (EPI == 3) C[o] = C[o] + v + (bias ? bias[n] : 0.0f);
                    else if (EPI == 4) C[o] = C[o] + geluf(v + bias[n]);
                    else if (EPI == 5) C[o] = softplusf(v + bias[n]);
                }
            }
        }
    }
}

// ---------------------------------------------------------------------------
// x_proj split-K: part[ks][1200][96] over K slice of 256, then reduce.
// ---------------------------------------------------------------------------
__global__ void __launch_bounds__(256)
gemm_xproj_part(const float* __restrict__ A, const float* __restrict__ B,
                float* __restrict__ part)
{
    __shared__ float As[16][33];
    __shared__ float Bs[96][33];
    const int m0  = blockIdx.x * 16;
    const int ks  = blockIdx.y;
    const int kbase = ks * (DINC / XKS);
    const int tid = threadIdx.x;
    const int ml  = tid >> 4;
    const int nb  = (tid & 15) * 6;

    float acc[6] = {0.f, 0.f, 0.f, 0.f, 0.f, 0.f};

    for (int k0 = kbase; k0 < kbase + DINC / XKS; k0 += 32) {
#pragma unroll
        for (int u = 0; u < 2; u++) {
            const int idx = tid + u * 256;
            const int r = idx >> 5, kk = idx & 31;
            As[r][kk] = A[(size_t)(m0 + r) * DINC + k0 + kk];
        }
#pragma unroll
        for (int u = 0; u < 12; u++) {
            const int idx = tid + u * 256;
            const int r = idx >> 5, kk = idx & 31;
            Bs[r][kk] = B[(size_t)r * DINC + k0 + kk];
        }
        __syncthreads();
#pragma unroll
        for (int kk = 0; kk < 32; kk++) {
            const float a = As[ml][kk];
#pragma unroll
            for (int j = 0; j < 6; j++)
                acc[j] = fmaf(a, Bs[nb + j][kk], acc[j]);
        }
        __syncthreads();
    }
#pragma unroll
    for (int j = 0; j < 6; j++)
        part[(size_t)ks * MTOT * XDBLC + (size_t)(m0 + ml) * XDBLC + nb + j] = acc[j];
}

__global__ void __launch_bounds__(256)
xproj_reduce(const float* __restrict__ part, float* __restrict__ C)
{
    const int idx = blockIdx.x * 256 + threadIdx.x;
    if (idx >= MTOT * XDBLC) return;
    float s = 0.f;
#pragma unroll
    for (int ks = 0; ks < XKS; ks++)
        s += part[(size_t)ks * MTOT * XDBLC + idx];
    C[idx] = s;
}

// ---------------------------------------------------------------------------
__global__ void __launch_bounds__(256)
ln_kernel(const float* __restrict__ x, const float* __restrict__ w,
          const float* __restrict__ b, float* __restrict__ out)
{
    const int row = blockIdx.x;
    const int tid = threadIdx.x;
    const float* xr = x + (size_t)row * DIMC;
    __shared__ float red[8];

    float v[4];
    float s = 0.f;
#pragma unroll
    for (int u = 0; u < 4; u++) { v[u] = xr[tid + u * 256]; s += v[u]; }
#pragma unroll
    for (int o = 16; o; o >>= 1) s += __shfl_xor_sync(0xffffffffu, s, o);
    if ((tid & 31) == 0) red[tid >> 5] = s;
    __syncthreads();
    float tot = 0.f;
#pragma unroll
    for (int u = 0; u < 8; u++) tot += red[u];
    const float mu = tot * (1.0f / 1024.0f);

    float s2 = 0.f;
#pragma unroll
    for (int u = 0; u < 4; u++) { const float d = v[u] - mu; s2 += d * d; }
    __syncthreads();
#pragma unroll
    for (int o = 16; o; o >>= 1) s2 += __shfl_xor_sync(0xffffffffu, s2, o);
    if ((tid & 31) == 0) red[tid >> 5] = s2;
    __syncthreads();
    float tot2 = 0.f;
#pragma unroll
    for (int u = 0; u < 8; u++) tot2 += red[u];
    const float rstd = rsqrtf(tot2 * (1.0f / 1024.0f) + 1e-5f);

    float* orow = out + (size_t)row * DIMC;
#pragma unroll
    for (int u = 0; u < 4; u++) {
        const int c = tid + u * 256;
        orow[c] = (v[u] - mu) * rstd * w[c] + b[c];
    }
}

// ---------------------------------------------------------------------------
__global__ void __launch_bounds__(256)
conv_kernel(const float* __restrict__ xz, const float* __restrict__ cw,
            const float* __restrict__ cb, float* __restrict__ out)
{
    const int m = blockIdx.x;
    const int d = blockIdx.y * 256 + threadIdx.x;
    const int b = m / SEQT, t = m % SEQT;
    float acc = cb[d];
#pragma unroll
    for (int j = 0; j < 4; j++) {
        const int tt = t + j - 3;
        if (tt >= 0)
            acc = fmaf(cw[d * 4 + j], xz[((size_t)(b * SEQT + tt)) * 4096 + d], acc);
    }
    out[(size_t)m * DINC + d] = siluf(acc);
}

// ---------------------------------------------------------------------------
__global__ void __launch_bounds__(256)
scan_kernel(const float* __restrict__ dt, const float* __restrict__ xc,
            const float* __restrict__ xdbl, const float* __restrict__ A_log,
            const float* __restrict__ Dw, const float* __restrict__ xz,
            float* __restrict__ y)
{
    const int tid = threadIdx.x;
    const int dl = tid & 15;
    const int s  = tid >> 4;
    const int d  = blockIdx.x * 16 + dl;
    const int b  = blockIdx.y;

    const float a = -expf(A_log[d * 16 + s]);
    float h = 0.f;
    float Dv = (s == 0) ? Dw[d] : 0.f;

    __shared__ float red[16][17];

    for (int t = 0; t < SEQT; t++) {
        const size_t base = (size_t)(b * SEQT + t);
        const float dtv = dt[base * DINC + d];
        const float xcv = xc[base * DINC + d];
        const float Bv  = xdbl[base * XDBLC + 64 + s];
        const float Cv  = xdbl[base * XDBLC + 80 + s];
        h = __expf(dtv * a) * h + dtv * Bv * xcv;
        red[s][dl] = h * Cv;
        __syncthreads();
        if (s == 0) {
            float sum = 0.f;
#pragma unroll
            for (int ss = 0; ss < 16; ss++) sum += red[ss][dl];
            const float zv = xz[base * 4096 + 2048 + d];
            y[base * DINC + d] = (sum + Dv * xcv) * (zv / (1.0f + __expf(-zv)));
        }
        __syncthreads();
    }
}

// ---------------------------------------------------------------------------
// Query-tiled causal attention (unchanged from R3).
// ---------------------------------------------------------------------------
#define QT 16
__global__ void __launch_bounds__(256)
attn_tile_kernel(const float* __restrict__ qkv, float* __restrict__ out)
{
    const int qt = blockIdx.x;
    const int h  = blockIdx.y;
    const int b  = blockIdx.z;
    const int i0 = qt * QT;
    const int tid  = threadIdx.x;
    const int qi   = tid >> 4;
    const int seg  = tid & 15;
    const int jmax = min(i0 + QT, SEQT);

    __shared__ __align__(16) float ks[2][4][16 * 68];
    __shared__ float S[QT][152];
    __shared__ float sinv[QT];

    const size_t base_bh = (size_t)(b * SEQT) * 12288 + (size_t)h * 1024;
    const int sts_off = (tid >> 4) * 68 + ((tid * 4) & 63);

    float4 qv[16];
    {
        const int row = min(i0 + qi, SEQT - 1);
        const float* qrow = qkv + (size_t)(b * SEQT + row) * 12288 + (size_t)h * 1024 + seg * 64;
#pragma unroll
        for (int u = 0; u < 16; u++)
            qv[u] = *reinterpret_cast<const float4*>(&qrow[u * 4]);
    }

    const int rounds = (jmax + 3) >> 2;
    float4 st[4];
#pragma unroll
    for (int u = 0; u < 4; u++)
        st[u] = (u < jmax)
              ? *reinterpret_cast<const float4*>(qkv + base_bh + (size_t)u * 12288 + 4096 + tid * 4)
              : make_float4(0.f, 0.f, 0.f, 0.f);
#pragma unroll
    for (int u = 0; u < 4; u++)
        *reinterpret_cast<float4*>(&ks[0][u][sts_off]) = st[u];
    __syncthreads();

    for (int r = 0; r < rounds; r++) {
        const int p = r & 1;
        if (r + 1 < rounds) {
#pragma unroll
            for (int u = 0; u < 4; u++) {
                const int j = (r + 1) * 4 + u;
                st[u] = (j < jmax)
                      ? *reinterpret_cast<const float4*>(qkv + base_bh + (size_t)j * 12288 + 4096 + tid * 4)
                      : make_float4(0.f, 0.f, 0.f, 0.f);
            }
        }
#pragma unroll
        for (int u = 0; u < 4; u++) {
            const int j = r * 4 + u;
            if (j < jmax) {
                const float* kp = &ks[p][u][seg * 68];
                float part = 0.f;
#pragma unroll
                for (int e = 0; e < 16; e++) {
                    const float4 k4 = *reinterpret_cast<const float4*>(&kp[e * 4]);
                    part = fmaf(qv[e].x, k4.x, part);
                    part = fmaf(qv[e].y, k4.y, part);
                    part = fmaf(qv[e].z, k4.z, part);
                    part = fmaf(qv[e].w, k4.w, part);
                }
                part += __shfl_xor_sync(0xffffffffu, part, 8);
                part += __shfl_xor_sync(0xffffffffu, part, 4);
                part += __shfl_xor_sync(0xffffffffu, part, 2);
                part += __shfl_xor_sync(0xffffffffu, part, 1);
                if (seg == 0)
                    S[qi][j] = (j <= i0 + qi) ? part * 0.03125f : -1e30f;
            }
        }
        if (r + 1 < rounds) {
#pragma unroll
            for (int u = 0; u < 4; u++)
                *reinterpret_cast<float4*>(&ks[p ^ 1][u][sts_off]) = st[u];
        }
        __syncthreads();
    }

    {
        const int w = tid >> 5, lane = tid & 31;
        for (int qq = w; qq < QT; qq += 8) {
            float m = -3.0e38f;
            for (int j = lane; j < jmax; j += 32) m = fmaxf(m, S[qq][j]);
#pragma unroll
            for (int o = 16; o; o >>= 1) m = fmaxf(m, __shfl_xor_sync(0xffffffffu, m, o));
            float sm = 0.f;
            for (int j = lane; j < jmax; j += 32) {
                const float e = __expf(S[qq][j] - m);
                S[qq][j] = e;
                sm += e;
            }
#pragma unroll
            for (int o = 16; o; o >>= 1) sm += __shfl_xor_sync(0xffffffffu, sm, o);
            if (lane == 0) sinv[qq] = 1.0f / sm;
        }
    }
    __syncthreads();

    float4 acc4[QT];
#pragma unroll
    for (int q = 0; q < QT; q++) acc4[q] = make_float4(0.f, 0.f, 0.f, 0.f);

    const float* vbase = qkv + base_bh + 8192 + tid * 4;
    for (int j0 = 0; j0 < jmax; j0 += 4) {
        float4 vv[4];
#pragma unroll
        for (int u = 0; u < 4; u++) {
            const int j = j0 + u;
            vv[u] = (j < jmax) ? *reinterpret_cast<const float4*>(vbase + (size_t)j * 12288)
                               : make_float4(0.f, 0.f, 0.f, 0.f);
        }
#pragma unroll
        for (int u = 0; u < 4; u++) {
            const int j = j0 + u;
            if (j < jmax) {
#pragma unroll
                for (int q = 0; q < QT; q++) {
                    const float pbc = S[q][j];
                    acc4[q].x = fmaf(pbc, vv[u].x, acc4[q].x);
                    acc4[q].y = fmaf(pbc, vv[u].y, acc4[q].y);
                    acc4[q].z = fmaf(pbc, vv[u].z, acc4[q].z);
                    acc4[q].w = fmaf(pbc, vv[u].w, acc4[q].w);
                }
            }
        }
    }

#pragma unroll
    for (int q = 0; q < QT; q++) {
        const int rowq = i0 + q;
        if (rowq < SEQT) {
            const float inv = sinv[q];
            float4 o;
            o.x = acc4[q].x * inv; o.y = acc4[q].y * inv;
            o.z = acc4[q].z * inv; o.w = acc4[q].w * inv;
            *reinterpret_cast<float4*>(out + (size_t)(b * SEQT + rowq) * INNERC
                                       + (size_t)h * 1024 + tid * 4) = o;
        }
    }
}

// ---------------------------------------------------------------------------
// Launch helpers: dynamic smem sizes per tile variant
// ---------------------------------------------------------------------------
static inline int smem_bytes(int BM) {
    return 4 * (BM * 20 + 128 * 20) * 4;
}

extern "C" void kernel_launch(void* const* d_in, const int* in_sizes, int n_in,
                              void* d_out, int out_size)
{
    const float* features    = (const float*)d_in[0];
    const float* mnorm_w     = (const float*)d_in[1];
    const float* mnorm_b     = (const float*)d_in[2];
    const float* in_proj_w   = (const float*)d_in[3];
    const float* conv_w      = (const float*)d_in[4];
    const float* conv_b      = (const float*)d_in[5];
    const float* x_proj_w    = (const float*)d_in[6];
    const float* dt_proj_w   = (const float*)d_in[7];
    const float* dt_proj_b   = (const float*)d_in[8];
    const float* A_log       = (const float*)d_in[9];
    const float* D_skip      = (const float*)d_in[10];
    const float* mamba_out_w = (const float*)d_in[11];
    const float* ln1_w       = (const float*)d_in[12];
    const float* ln1_b       = (const float*)d_in[13];
    const float* qkv_w       = (const float*)d_in[14];
    const float* attn_out_w  = (const float*)d_in[15];
    const float* attn_out_b  = (const float*)d_in[16];
    const float* ln2_w       = (const float*)d_in[17];
    const float* ln2_b       = (const float*)d_in[18];
    const float* ffn_w1      = (const float*)d_in[19];
    const float* ffn_b1      = (const float*)d_in[20];
    const float* ffn_w2      = (const float*)d_in[21];
    const float* ffn_b2      = (const float*)d_in[22];

    float *p_norm, *p_xz, *p_xc, *p_xdbl, *p_xpart, *p_dt, *p_y, *p_qkv, *p_attn, *p_ffn;
    cudaGetSymbolAddress((void**)&p_norm,  g_norm);
    cudaGetSymbolAddress((void**)&p_xz,    g_xz);
    cudaGetSymbolAddress((void**)&p_xc,    g_xc);
    cudaGetSymbolAddress((void**)&p_xdbl,  g_xdbl);
    cudaGetSymbolAddress((void**)&p_xpart, g_xpart);
    cudaGetSymbolAddress((void**)&p_dt,    g_dt);
    cudaGetSymbolAddress((void**)&p_y,     g_y);
    cudaGetSymbolAddress((void**)&p_qkv,   g_qkv);
    cudaGetSymbolAddress((void**)&p_attn,  g_attn);
    cudaGetSymbolAddress((void**)&p_ffn,   g_ffn);

    const int SM64  = smem_bytes(64);    // 61440
    const int SM128 = smem_bytes(128);   // 81920
    cudaFuncSetAttribute(gemm_tc<0,  64>, cudaFuncAttributeMaxDynamicSharedMemorySize, SM64);
    cudaFuncSetAttribute(gemm_tc<2,  64>, cudaFuncAttributeMaxDynamicSharedMemorySize, SM64);
    cudaFuncSetAttribute(gemm_tc<3,  64>, cudaFuncAttributeMaxDynamicSharedMemorySize, SM64);
    cudaFuncSetAttribute(gemm_tc<4,  64>, cudaFuncAttributeMaxDynamicSharedMemorySize, SM64);
    cudaFuncSetAttribute(gemm_tc<5,  64>, cudaFuncAttributeMaxDynamicSharedMemorySize, SM64);
    cudaFuncSetAttribute(gemm_tc<0, 128>, cudaFuncAttributeMaxDynamicSharedMemorySize, SM128);

    float* X = (float*)d_out;
    cudaMemcpyAsync(X, features, sizeof(float) * (size_t)MTOT * DIMC,
                    cudaMemcpyDeviceToDevice);

    for (int i = 0; i < DEPTHC; i++) {
        // ---- Mamba ----
        ln_kernel<<<MTOT, 256>>>(X, mnorm_w + i * DIMC, mnorm_b + i * DIMC, p_norm);
        gemm_tc<0, 64><<<dim3(32, 19), 256, SM64>>>(p_norm, DIMC,
                in_proj_w + (size_t)i * 4096 * DIMC, DIMC,
                nullptr, p_xz, 4096, MTOT, 4096, DIMC);
        conv_kernel<<<dim3(MTOT, 8), 256>>>(p_xz, conv_w + (size_t)i * DINC * 4,
                                            conv_b + i * DINC, p_xc);
        gemm_xproj_part<<<dim3(75, XKS), 256>>>(p_xc,
                x_proj_w + (size_t)i * XDBLC * DINC, p_xpart);
        xproj_reduce<<<(MTOT * XDBLC + 255) / 256, 256>>>(p_xpart, p_xdbl);
        gemm_tc<5, 64><<<dim3(16, 19), 256, SM64>>>(p_xdbl, XDBLC,
                dt_proj_w + (size_t)i * DINC * DTRANK, DTRANK,
                dt_proj_b + i * DINC, p_dt, DINC, MTOT, DINC, DTRANK);
        scan_kernel<<<dim3(128, BATCH), 256>>>(p_dt, p_xc, p_xdbl,
                A_log + (size_t)i * DINC * DSTATE,
                D_skip + i * DINC, p_xz, p_y);
        gemm_tc<3, 64><<<dim3(8, 19), 256, SM64>>>(p_y, DINC,
                mamba_out_w + (size_t)i * DIMC * DINC, DINC,
                nullptr, X, DIMC, MTOT, DIMC, DINC);

        // ---- Attention ----
        ln_kernel<<<MTOT, 256>>>(X, ln1_w + i * DIMC, ln1_b + i * DIMC, p_norm);
        gemm_tc<0, 128><<<dim3(96, 10), 256, SM128>>>(p_norm, DIMC,
                qkv_w + (size_t)i * 3 * INNERC * DIMC, DIMC,
                nullptr, p_qkv, 3 * INNERC, MTOT, 3 * INNERC, DIMC);
        attn_tile_kernel<<<dim3(10, 4, BATCH), 256>>>(p_qkv, p_attn);
        gemm_tc<4, 64><<<dim3(8, 19), 256, SM64>>>(p_attn, INNERC,
                attn_out_w + (size_t)i * DIMC * INNERC, INNERC,
                attn_out_b + i * DIMC, X, DIMC, MTOT, DIMC, INNERC);

        // ---- FFN ----
        ln_kernel<<<MTOT, 256>>>(X, ln2_w + i * DIMC, ln2_b + i * DIMC, p_norm);
        gemm_tc<2, 64><<<dim3(32, 19), 256, SM64>>>(p_norm, DIMC,
                ffn_w1 + (size_t)i * MLPC * DIMC, DIMC,
                ffn_b1 + i * MLPC, p_ffn, MLPC, MTOT, MLPC, DIMC);
        gemm_tc<3, 64><<<dim3(8, 19), 256, SM64>>>(p_ffn, MLPC,
                ffn_w2 + (size_t)i * DIMC * MLPC, MLPC,
                ffn_b2 + i * DIMC, X, DIMC, MTOT, DIMC, MLPC);
    }
}

// round 5
// speedup vs baseline: 3.5306x; 1.0238x over previous
#include <cuda_runtime.h>
#include <math.h>
#include <stdint.h>

// ---------------------------------------------------------------------------
#define BATCH   8
#define SEQT    150
#define MTOT    1200
#define DIMC    1024
#define DINC    2048
#define DSTATE  16
#define DTRANK  64
#define XDBLC   96
#define INNERC  4096
#define MLPC    4096
#define DEPTHC  5
#define XKS     8

// ---------------------------------------------------------------------------
__device__ float g_norm [MTOT * DIMC];
__device__ float g_xz   [MTOT * 2 * DINC];
__device__ float g_xc   [MTOT * DINC];
__device__ float g_xdbl [MTOT * XDBLC];
__device__ float g_xpart[XKS * MTOT * XDBLC];
__device__ float g_dt   [MTOT * DINC];
__device__ float g_y    [MTOT * DINC];
__device__ float g_qkv  [MTOT * 3 * INNERC];
__device__ float g_attn [MTOT * INNERC];
__device__ float g_ffn  [MTOT * MLPC];

// ---------------------------------------------------------------------------
__device__ __forceinline__ float geluf(float x) {
    return 0.5f * x * (1.0f + erff(x * 0.70710678118654752f));
}
__device__ __forceinline__ float softplusf(float x) {
    return fmaxf(x, 0.0f) + log1pf(__expf(-fabsf(x)));
}
__device__ __forceinline__ float siluf(float x) {
    return x / (1.0f + __expf(-x));
}
// round-to-nearest tf32, returned as fp32 (low 13 mantissa bits zero)
__device__ __forceinline__ float rtf(float x) {
    uint32_t r;
    asm("cvt.rna.tf32.f32 %0, %1;" : "=r"(r) : "f"(x));
    return __uint_as_float(r);
}
__device__ __forceinline__ void mma_tf32(float c[4],
                                         uint32_t a0, uint32_t a1, uint32_t a2, uint32_t a3,
                                         uint32_t b0, uint32_t b1) {
    asm volatile(
        "mma.sync.aligned.m16n8k8.row.col.f32.tf32.tf32.f32 "
        "{%0,%1,%2,%3}, {%4,%5,%6,%7}, {%8,%9}, {%0,%1,%2,%3};"
        : "+f"(c[0]), "+f"(c[1]), "+f"(c[2]), "+f"(c[3])
        : "r"(a0), "r"(a1), "r"(a2), "r"(a3), "r"(b0), "r"(b1));
}
__device__ __forceinline__ void cp16(uint32_t dst, const float* src, int sz) {
    asm volatile("cp.async.cg.shared.global [%0], [%1], 16, %2;"
                 :: "r"(dst), "l"(src), "r"(sz));
}

// ---------------------------------------------------------------------------
// 4-stage cp.async TF32 tensor-core NT GEMM. No in-loop cvt: A operands are
// pre-rounded to tf32 by producer kernels; B (weights) relies on the HW
// truncating fp32 -> tf32 inside HMMA.
// ---------------------------------------------------------------------------
template <int EPI, int BM>
__global__ void __launch_bounds__(256, 2)
gemm_tc(const float* __restrict__ A, int lda,
        const float* __restrict__ B, int ldb,
        const float* __restrict__ bias,
        float* __restrict__ C, int ldc,
        int M, int N, int K)
{
    constexpr int PAD = 20;
    constexpr int MI  = 2;
    constexpr int NJ  = (BM == 128) ? 8 : 4;
    constexpr int ARQ = BM / 64;

    extern __shared__ float smem[];
    float* sA = smem;
    float* sB = smem + 4 * BM * PAD;

    const int m0   = blockIdx.y * BM;
    const int n0   = blockIdx.x * 128;
    const int tid  = threadIdx.x;
    const int lane = tid & 31;
    const int warp = tid >> 5;
    const int wm   = (BM == 128) ? (warp & 3) : (warp & 1);
    const int wn   = (BM == 128) ? (warp >> 2) : (warp >> 1);
    const int ar   = lane >> 2;
    const int ac   = lane & 3;

    const int NIT = K >> 4;

    float acc[MI][NJ][4];
#pragma unroll
    for (int i = 0; i < MI; i++)
#pragma unroll
        for (int j = 0; j < NJ; j++)
#pragma unroll
            for (int r = 0; r < 4; r++) acc[i][j][r] = 0.0f;

    auto issue = [&](int s, int k0, bool real) {
        if (real) {
#pragma unroll
            for (int r = 0; r < ARQ; r++) {
                const int idx = tid + r * 256;
                const int row = idx >> 2;
                const int kq  = (idx & 3) << 2;
                const float* src = &A[(size_t)(m0 + row) * lda + k0 + kq];
                uint32_t dst = (uint32_t)__cvta_generic_to_shared(
                    &sA[(s * BM + row) * PAD + kq]);
                cp16(dst, src, (m0 + row < M) ? 16 : 0);
            }
#pragma unroll
            for (int r = 0; r < 2; r++) {
                const int idx = tid + r * 256;
                const int row = idx >> 2;
                const int kq  = (idx & 3) << 2;
                const float* src = &B[(size_t)(n0 + row) * ldb + k0 + kq];
                uint32_t dst = (uint32_t)__cvta_generic_to_shared(
                    &sB[(s * 128 + row) * PAD + kq]);
                cp16(dst, src, (n0 + row < N) ? 16 : 0);
            }
        }
        asm volatile("cp.async.commit_group;");
    };

    issue(0, 0, true);
    issue(1, 16, 1 < NIT);
    issue(2, 32, 2 < NIT);

    for (int it = 0; it < NIT; it++) {
        const int p = it & 3;
        asm volatile("cp.async.wait_group 2;");
        __syncthreads();
        issue((it + 3) & 3, (it + 3) << 4, (it + 3) < NIT);

        const float* pa = &sA[p * BM * PAD];
        const float* pb = &sB[p * 128 * PAD];
#pragma unroll
        for (int ks = 0; ks < 2; ks++) {
            const int kk = ks * 8;
            uint32_t af[MI][4], bf[NJ][2];
#pragma unroll
            for (int i = 0; i < MI; i++) {
                const int r = wm * 32 + i * 16 + ar;
                af[i][0] = __float_as_uint(pa[(r    ) * PAD + kk + ac    ]);
                af[i][1] = __float_as_uint(pa[(r + 8) * PAD + kk + ac    ]);
                af[i][2] = __float_as_uint(pa[(r    ) * PAD + kk + ac + 4]);
                af[i][3] = __float_as_uint(pa[(r + 8) * PAD + kk + ac + 4]);
            }
#pragma unroll
            for (int j = 0; j < NJ; j++) {
                const int c = wn * (8 * NJ) + j * 8 + ar;
                bf[j][0] = __float_as_uint(pb[c * PAD + kk + ac    ]);
                bf[j][1] = __float_as_uint(pb[c * PAD + kk + ac + 4]);
            }
#pragma unroll
            for (int i = 0; i < MI; i++)
#pragma unroll
                for (int j = 0; j < NJ; j++)
                    mma_tf32(acc[i][j], af[i][0], af[i][1], af[i][2], af[i][3],
                             bf[j][0], bf[j][1]);
        }
        __syncthreads();
    }

#pragma unroll
    for (int i = 0; i < MI; i++) {
#pragma unroll
        for (int j = 0; j < NJ; j++) {
            const int mb = m0 + wm * 32 + i * 16 + ar;
            const int nb = n0 + wn * (8 * NJ) + j * 8 + ac * 2;
#pragma unroll
            for (int r2 = 0; r2 < 2; r2++) {
#pragma unroll
                for (int c2 = 0; c2 < 2; c2++) {
                    const int m = mb + r2 * 8;
                    const int n = nb + c2;
                    if (m >= M || n >= N) continue;
                    const size_t o = (size_t)m * ldc + n;
                    float v = acc[i][j][r2 * 2 + c2];
                    if (EPI == 0)      C[o] = v;
                    else if (EPI == 1) C[o] = v + bias[n];
                    else if (EPI == 2) C[o] = rtf(geluf(v + bias[n]));  // feeds ffn2 A
                    else if (EPI == 3) C[o] = C[o] + v + (bias ? bias[n] : 0.0f);
                    else if (EPI == 4) C[o] = C[o] + geluf(v + bias[n]);
                    else if (EPI == 5) C[o] = softplusf(v + bias[n]);
                }
            }
        }
    }
}

// ---------------------------------------------------------------------------
// x_proj split-K + reduce (reduce pre-rounds for dt_proj's A operand)
// ---------------------------------------------------------------------------
__global__ void __launch_bounds__(256)
gemm_xproj_part(const float* __restrict__ A, const float* __restrict__ B,
                float* __restrict__ part)
{
    __shared__ float As[16][33];
    __shared__ float Bs[96][33];
    const int m0  = blockIdx.x * 16;
    const int ks  = blockIdx.y;
    const int kbase = ks * (DINC / XKS);
    const int tid = threadIdx.x;
    const int ml  = tid >> 4;
    const int nb  = (tid & 15) * 6;

    float acc[6] = {0.f, 0.f, 0.f, 0.f, 0.f, 0.f};

    for (int k0 = kbase; k0 < kbase + DINC / XKS; k0 += 32) {
#pragma unroll
        for (int u = 0; u < 2; u++) {
            const int idx = tid + u * 256;
            const int r = idx >> 5, kk = idx & 31;
            As[r][kk] = A[(size_t)(m0 + r) * DINC + k0 + kk];
        }
#pragma unroll
        for (int u = 0; u < 12; u++) {
            const int idx = tid + u * 256;
            const int r = idx >> 5, kk = idx & 31;
            Bs[r][kk] = B[(size_t)r * DINC + k0 + kk];
        }
        __syncthreads();
#pragma unroll
        for (int kk = 0; kk < 32; kk++) {
            const float a = As[ml][kk];
#pragma unroll
            for (int j = 0; j < 6; j++)
                acc[j] = fmaf(a, Bs[nb + j][kk], acc[j]);
        }
        __syncthreads();
    }
#pragma unroll
    for (int j = 0; j < 6; j++)
        part[(size_t)ks * MTOT * XDBLC + (size_t)(m0 + ml) * XDBLC + nb + j] = acc[j];
}

__global__ void __launch_bounds__(256)
xproj_reduce(const float* __restrict__ part, float* __restrict__ C)
{
    const int idx = blockIdx.x * 256 + threadIdx.x;
    if (idx >= MTOT * XDBLC) return;
    float s = 0.f;
#pragma unroll
    for (int ks = 0; ks < XKS; ks++)
        s += part[(size_t)ks * MTOT * XDBLC + idx];
    C[idx] = rtf(s);
}

// ---------------------------------------------------------------------------
// LayerNorm (output pre-rounded to tf32: feeds GEMM A operands only)
// ---------------------------------------------------------------------------
__global__ void __launch_bounds__(256)
ln_kernel(const float* __restrict__ x, const float* __restrict__ w,
          const float* __restrict__ b, float* __restrict__ out)
{
    const int row = blockIdx.x;
    const int tid = threadIdx.x;
    const float* xr = x + (size_t)row * DIMC;
    __shared__ float red[8];

    float v[4];
    float s = 0.f;
#pragma unroll
    for (int u = 0; u < 4; u++) { v[u] = xr[tid + u * 256]; s += v[u]; }
#pragma unroll
    for (int o = 16; o; o >>= 1) s += __shfl_xor_sync(0xffffffffu, s, o);
    if ((tid & 31) == 0) red[tid >> 5] = s;
    __syncthreads();
    float tot = 0.f;
#pragma unroll
    for (int u = 0; u < 8; u++) tot += red[u];
    const float mu = tot * (1.0f / 1024.0f);

    float s2 = 0.f;
#pragma unroll
    for (int u = 0; u < 4; u++) { const float d = v[u] - mu; s2 += d * d; }
    __syncthreads();
#pragma unroll
    for (int o = 16; o; o >>= 1) s2 += __shfl_xor_sync(0xffffffffu, s2, o);
    if ((tid & 31) == 0) red[tid >> 5] = s2;
    __syncthreads();
    float tot2 = 0.f;
#pragma unroll
    for (int u = 0; u < 8; u++) tot2 += red[u];
    const float rstd = rsqrtf(tot2 * (1.0f / 1024.0f) + 1e-5f);

    float* orow = out + (size_t)row * DIMC;
#pragma unroll
    for (int u = 0; u < 4; u++) {
        const int c = tid + u * 256;
        orow[c] = rtf((v[u] - mu) * rstd * w[c] + b[c]);
    }
}

// ---------------------------------------------------------------------------
__global__ void __launch_bounds__(256)
conv_kernel(const float* __restrict__ xz, const float* __restrict__ cw,
            const float* __restrict__ cb, float* __restrict__ out)
{
    const int m = blockIdx.x;
    const int d = blockIdx.y * 256 + threadIdx.x;
    const int b = m / SEQT, t = m % SEQT;
    float acc = cb[d];
#pragma unroll
    for (int j = 0; j < 4; j++) {
        const int tt = t + j - 3;
        if (tt >= 0)
            acc = fmaf(cw[d * 4 + j], xz[((size_t)(b * SEQT + tt)) * 4096 + d], acc);
    }
    out[(size_t)m * DINC + d] = siluf(acc);
}

// ---------------------------------------------------------------------------
// Barrier-free selective scan. Warp = 2 d-lanes x 16 states; state reduction
// via 4 shfl.xor. No smem, no __syncthreads. y pre-rounded (feeds mamba_out A).
// ---------------------------------------------------------------------------
__global__ void __launch_bounds__(256)
scan_kernel(const float* __restrict__ dt, const float* __restrict__ xc,
            const float* __restrict__ xdbl, const float* __restrict__ A_log,
            const float* __restrict__ Dw, const float* __restrict__ xz,
            float* __restrict__ y)
{
    const int tid  = threadIdx.x;
    const int lane = tid & 31;
    const int wrp  = tid >> 5;          // 0..7
    const int s    = lane & 15;
    const int dsub = lane >> 4;         // 0/1
    const int d    = blockIdx.x * 16 + wrp * 2 + dsub;
    const int b    = blockIdx.y;

    const float a  = -expf(A_log[d * 16 + s]);
    const float Dv = Dw[d];
    float h = 0.f;

    for (int t = 0; t < SEQT; t++) {
        const size_t base = (size_t)(b * SEQT + t);
        const float dtv = dt[base * DINC + d];
        const float xcv = xc[base * DINC + d];
        const float Bv  = xdbl[base * XDBLC + 64 + s];
        const float Cv  = xdbl[base * XDBLC + 80 + s];
        h = __expf(dtv * a) * h + dtv * Bv * xcv;
        float p = h * Cv;
        p += __shfl_xor_sync(0xffffffffu, p, 1);
        p += __shfl_xor_sync(0xffffffffu, p, 2);
        p += __shfl_xor_sync(0xffffffffu, p, 4);
        p += __shfl_xor_sync(0xffffffffu, p, 8);
        if (s == 0) {
            const float zv = xz[base * 4096 + 2048 + d];
            y[base * DINC + d] = rtf((p + Dv * xcv) * (zv / (1.0f + __expf(-zv))));
        }
    }
}

// ---------------------------------------------------------------------------
// Query-tiled causal attention (outputs pre-rounded: feed attn_out A)
// ---------------------------------------------------------------------------
#define QT 16
__global__ void __launch_bounds__(256)
attn_tile_kernel(const float* __restrict__ qkv, float* __restrict__ out)
{
    const int qt = blockIdx.x;
    const int h  = blockIdx.y;
    const int b  = blockIdx.z;
    const int i0 = qt * QT;
    const int tid  = threadIdx.x;
    const int qi   = tid >> 4;
    const int seg  = tid & 15;
    const int jmax = min(i0 + QT, SEQT);

    __shared__ __align__(16) float ks[2][4][16 * 68];
    __shared__ float S[QT][152];
    __shared__ float sinv[QT];

    const size_t base_bh = (size_t)(b * SEQT) * 12288 + (size_t)h * 1024;
    const int sts_off = (tid >> 4) * 68 + ((tid * 4) & 63);

    float4 qv[16];
    {
        const int row = min(i0 + qi, SEQT - 1);
        const float* qrow = qkv + (size_t)(b * SEQT + row) * 12288 + (size_t)h * 1024 + seg * 64;
#pragma unroll
        for (int u = 0; u < 16; u++)
            qv[u] = *reinterpret_cast<const float4*>(&qrow[u * 4]);
    }

    const int rounds = (jmax + 3) >> 2;
    float4 st[4];
#pragma unroll
    for (int u = 0; u < 4; u++)
        st[u] = (u < jmax)
              ? *reinterpret_cast<const float4*>(qkv + base_bh + (size_t)u * 12288 + 4096 + tid * 4)
              : make_float4(0.f, 0.f, 0.f, 0.f);
#pragma unroll
    for (int u = 0; u < 4; u++)
        *reinterpret_cast<float4*>(&ks[0][u][sts_off]) = st[u];
    __syncthreads();

    for (int r = 0; r < rounds; r++) {
        const int p = r & 1;
        if (r + 1 < rounds) {
#pragma unroll
            for (int u = 0; u < 4; u++) {
                const int j = (r + 1) * 4 + u;
                st[u] = (j < jmax)
                      ? *reinterpret_cast<const float4*>(qkv + base_bh + (size_t)j * 12288 + 4096 + tid * 4)
                      : make_float4(0.f, 0.f, 0.f, 0.f);
            }
        }
#pragma unroll
        for (int u = 0; u < 4; u++) {
            const int j = r * 4 + u;
            if (j < jmax) {
                const float* kp = &ks[p][u][seg * 68];
                float part = 0.f;
#pragma unroll
                for (int e = 0; e < 16; e++) {
                    const float4 k4 = *reinterpret_cast<const float4*>(&kp[e * 4]);
                    part = fmaf(qv[e].x, k4.x, part);
                    part = fmaf(qv[e].y, k4.y, part);
                    part = fmaf(qv[e].z, k4.z, part);
                    part = fmaf(qv[e].w, k4.w, part);
                }
                part += __shfl_xor_sync(0xffffffffu, part, 8);
                part += __shfl_xor_sync(0xffffffffu, part, 4);
                part += __shfl_xor_sync(0xffffffffu, part, 2);
                part += __shfl_xor_sync(0xffffffffu, part, 1);
                if (seg == 0)
                    S[qi][j] = (j <= i0 + qi) ? part * 0.03125f : -1e30f;
            }
        }
        if (r + 1 < rounds) {
#pragma unroll
            for (int u = 0; u < 4; u++)
                *reinterpret_cast<float4*>(&ks[p ^ 1][u][sts_off]) = st[u];
        }
        __syncthreads();
    }

    {
        const int w = tid >> 5, lane = tid & 31;
        for (int qq = w; qq < QT; qq += 8) {
            float m = -3.0e38f;
            for (int j = lane; j < jmax; j += 32) m = fmaxf(m, S[qq][j]);
#pragma unroll
            for (int o = 16; o; o >>= 1) m = fmaxf(m, __shfl_xor_sync(0xffffffffu, m, o));
            float sm = 0.f;
            for (int j = lane; j < jmax; j += 32) {
                const float e = __expf(S[qq][j] - m);
                S[qq][j] = e;
                sm += e;
            }
#pragma unroll
            for (int o = 16; o; o >>= 1) sm += __shfl_xor_sync(0xffffffffu, sm, o);
            if (lane == 0) sinv[qq] = 1.0f / sm;
        }
    }
    __syncthreads();

    float4 acc4[QT];
#pragma unroll
    for (int q = 0; q < QT; q++) acc4[q] = make_float4(0.f, 0.f, 0.f, 0.f);

    const float* vbase = qkv + base_bh + 8192 + tid * 4;
    for (int j0 = 0; j0 < jmax; j0 += 4) {
        float4 vv[4];
#pragma unroll
        for (int u = 0; u < 4; u++) {
            const int j = j0 + u;
            vv[u] = (j < jmax) ? *reinterpret_cast<const float4*>(vbase + (size_t)j * 12288)
                               : make_float4(0.f, 0.f, 0.f, 0.f);
        }
#pragma unroll
        for (int u = 0; u < 4; u++) {
            const int j = j0 + u;
            if (j < jmax) {
#pragma unroll
                for (int q = 0; q < QT; q++) {
                    const float pbc = S[q][j];
                    acc4[q].x = fmaf(pbc, vv[u].x, acc4[q].x);
                    acc4[q].y = fmaf(pbc, vv[u].y, acc4[q].y);
                    acc4[q].z = fmaf(pbc, vv[u].z, acc4[q].z);
                    acc4[q].w = fmaf(pbc, vv[u].w, acc4[q].w);
                }
            }
        }
    }

#pragma unroll
    for (int q = 0; q < QT; q++) {
        const int rowq = i0 + q;
        if (rowq < SEQT) {
            const float inv = sinv[q];
            float4 o;
            o.x = rtf(acc4[q].x * inv); o.y = rtf(acc4[q].y * inv);
            o.z = rtf(acc4[q].z * inv); o.w = rtf(acc4[q].w * inv);
            *reinterpret_cast<float4*>(out + (size_t)(b * SEQT + rowq) * INNERC
                                       + (size_t)h * 1024 + tid * 4) = o;
        }
    }
}

// ---------------------------------------------------------------------------
static inline int smem_bytes(int BM) {
    return 4 * (BM * 20 + 128 * 20) * 4;
}

extern "C" void kernel_launch(void* const* d_in, const int* in_sizes, int n_in,
                              void* d_out, int out_size)
{
    const float* features    = (const float*)d_in[0];
    const float* mnorm_w     = (const float*)d_in[1];
    const float* mnorm_b     = (const float*)d_in[2];
    const float* in_proj_w   = (const float*)d_in[3];
    const float* conv_w      = (const float*)d_in[4];
    const float* conv_b      = (const float*)d_in[5];
    const float* x_proj_w    = (const float*)d_in[6];
    const float* dt_proj_w   = (const float*)d_in[7];
    const float* dt_proj_b   = (const float*)d_in[8];
    const float* A_log       = (const float*)d_in[9];
    const float* D_skip      = (const float*)d_in[10];
    const float* mamba_out_w = (const float*)d_in[11];
    const float* ln1_w       = (const float*)d_in[12];
    const float* ln1_b       = (const float*)d_in[13];
    const float* qkv_w       = (const float*)d_in[14];
    const float* attn_out_w  = (const float*)d_in[15];
    const float* attn_out_b  = (const float*)d_in[16];
    const float* ln2_w       = (const float*)d_in[17];
    const float* ln2_b       = (const float*)d_in[18];
    const float* ffn_w1      = (const float*)d_in[19];
    const float* ffn_b1      = (const float*)d_in[20];
    const float* ffn_w2      = (const float*)d_in[21];
    const float* ffn_b2      = (const float*)d_in[22];

    float *p_norm, *p_xz, *p_xc, *p_xdbl, *p_xpart, *p_dt, *p_y, *p_qkv, *p_attn, *p_ffn;
    cudaGetSymbolAddress((void**)&p_norm,  g_norm);
    cudaGetSymbolAddress((void**)&p_xz,    g_xz);
    cudaGetSymbolAddress((void**)&p_xc,    g_xc);
    cudaGetSymbolAddress((void**)&p_xdbl,  g_xdbl);
    cudaGetSymbolAddress((void**)&p_xpart, g_xpart);
    cudaGetSymbolAddress((void**)&p_dt,    g_dt);
    cudaGetSymbolAddress((void**)&p_y,     g_y);
    cudaGetSymbolAddress((void**)&p_qkv,   g_qkv);
    cudaGetSymbolAddress((void**)&p_attn,  g_attn);
    cudaGetSymbolAddress((void**)&p_ffn,   g_ffn);

    const int SM64  = smem_bytes(64);
    const int SM128 = smem_bytes(128);
    cudaFuncSetAttribute(gemm_tc<0,  64>, cudaFuncAttributeMaxDynamicSharedMemorySize, SM64);
    cudaFuncSetAttribute(gemm_tc<2,  64>, cudaFuncAttributeMaxDynamicSharedMemorySize, SM64);
    cudaFuncSetAttribute(gemm_tc<3,  64>, cudaFuncAttributeMaxDynamicSharedMemorySize, SM64);
    cudaFuncSetAttribute(gemm_tc<4,  64>, cudaFuncAttributeMaxDynamicSharedMemorySize, SM64);
    cudaFuncSetAttribute(gemm_tc<5,  64>, cudaFuncAttributeMaxDynamicSharedMemorySize, SM64);
    cudaFuncSetAttribute(gemm_tc<0, 128>, cudaFuncAttributeMaxDynamicSharedMemorySize, SM128);

    float* X = (float*)d_out;
    cudaMemcpyAsync(X, features, sizeof(float) * (size_t)MTOT * DIMC,
                    cudaMemcpyDeviceToDevice);

    for (int i = 0; i < DEPTHC; i++) {
        // ---- Mamba ----
        ln_kernel<<<MTOT, 256>>>(X, mnorm_w + i * DIMC, mnorm_b + i * DIMC, p_norm);
        gemm_tc<0, 64><<<dim3(32, 19), 256, SM64>>>(p_norm, DIMC,
                in_proj_w + (size_t)i * 4096 * DIMC, DIMC,
                nullptr, p_xz, 4096, MTOT, 4096, DIMC);
        conv_kernel<<<dim3(MTOT, 8), 256>>>(p_xz, conv_w + (size_t)i * DINC * 4,
                                            conv_b + i * DINC, p_xc);
        gemm_xproj_part<<<dim3(75, XKS), 256>>>(p_xc,
                x_proj_w + (size_t)i * XDBLC * DINC, p_xpart);
        xproj_reduce<<<(MTOT * XDBLC + 255) / 256, 256>>>(p_xpart, p_xdbl);
        gemm_tc<5, 64><<<dim3(16, 19), 256, SM64>>>(p_xdbl, XDBLC,
                dt_proj_w + (size_t)i * DINC * DTRANK, DTRANK,
                dt_proj_b + i * DINC, p_dt, DINC, MTOT, DINC, DTRANK);
        scan_kernel<<<dim3(128, BATCH), 256>>>(p_dt, p_xc, p_xdbl,
                A_log + (size_t)i * DINC * DSTATE,
                D_skip + i * DINC, p_xz, p_y);
        gemm_tc<3, 64><<<dim3(8, 19), 256, SM64>>>(p_y, DINC,
                mamba_out_w + (size_t)i * DIMC * DINC, DINC,
                nullptr, X, DIMC, MTOT, DIMC, DINC);

        // ---- Attention ----
        ln_kernel<<<MTOT, 256>>>(X, ln1_w + i * DIMC, ln1_b + i * DIMC, p_norm);
        gemm_tc<0, 128><<<dim3(96, 10), 256, SM128>>>(p_norm, DIMC,
                qkv_w + (size_t)i * 3 * INNERC * DIMC, DIMC,
                nullptr, p_qkv, 3 * INNERC, MTOT, 3 * INNERC, DIMC);
        attn_tile_kernel<<<dim3(10, 4, BATCH), 256>>>(p_qkv, p_attn);
        gemm_tc<4, 64><<<dim3(8, 19), 256, SM64>>>(p_attn, INNERC,
                attn_out_w + (size_t)i * DIMC * INNERC, INNERC,
                attn_out_b + i * DIMC, X, DIMC, MTOT, DIMC, INNERC);

        // ---- FFN ----
        ln_kernel<<<MTOT, 256>>>(X, ln2_w + i * DIMC, ln2_b + i * DIMC, p_norm);
        gemm_tc<2, 64><<<dim3(32, 19), 256, SM64>>>(p_norm, DIMC,
                ffn_w1 + (size_t)i * MLPC * DIMC, DIMC,
                ffn_b1 + i * MLPC, p_ffn, MLPC, MTOT, MLPC, DIMC);
        gemm_tc<3, 64><<<dim3(8, 19), 256, SM64>>>(p_ffn, MLPC,
                ffn_w2 + (size_t)i * DIMC * MLPC, MLPC,
                ffn_b2 + i * DIMC, X, DIMC, MTOT, DIMC, MLPC);
    }
}